// round 9
// baseline (speedup 1.0000x reference)
#include <cuda_runtime.h>
#include <math.h>
#include <stdint.h>

#define VV 50257
#define DD 128
#define NN 256
#define LL 2
#define BB 8
#define SS 256
#define MM (BB*SS)          // 2048
#define RESN 4096
#define HOFF ((size_t)MM * VV)

#define PHI_F 1.6180339887498949f
#define CSC_F 651.8986469044033f          // RES / (2*pi)
#define ANG_F 0.0015339807878856412f      // 2*pi / RES

// ---------------- scratch (static device memory; no allocations) -----------
__device__ float2 g_tab[RESN];
__device__ float  g_X[MM * DD];          // post-MLP: holds tf32-rounded values
__device__ float  g_Wt [LL * DD * NN];   // [l][k][j]  (transposed layer_W)
__device__ float  g_Wrt[LL * NN * DD];   // [l][j][d]  (transposed layer_Wr)
__device__ float  g_Wit[LL * NN * DD];   // [l][j][d]  (transposed layer_Wi)

__device__ __forceinline__ unsigned f2tf32(float v) {
    unsigned u;
    asm("cvt.rna.tf32.f32 %0, %1;" : "=r"(u) : "f"(v));
    return u;
}

// ------- ARM optimized-routines AdvSIMD sinf/cosf (glibc libmvec) ----------
// VALIDATED in R6 (passed). Do not modify.
#define AOR_INVPI  0x1.45f306p-2f
#define AOR_PI1    0x1.921fb6p+1f
#define AOR_PI2   -0x1.777a5cp-24f
#define AOR_PI3   -0x1.ee59dap-49f
#define AOR_SHIFT  0x1.8p+23f
#define AOR_P0    -0x1.555548p-3f
#define AOR_P1     0x1.110df4p-7f
#define AOR_P2    -0x1.9f42eap-13f
#define AOR_P3     0x1.5b2e76p-19f

__device__ __forceinline__ float aor_sin_core(float r, unsigned odd) {
    float r2 = __fmul_rn(r, r);
    float y  = __fmaf_rn(AOR_P3, r2, AOR_P2);
    y = __fmaf_rn(y, r2, AOR_P1);
    y = __fmaf_rn(y, r2, AOR_P0);
    y = __fmaf_rn(__fmul_rn(y, r2), r, r);
    return __uint_as_float(__float_as_uint(y) ^ odd);
}

__device__ __forceinline__ float aor_sinf(float x) {
    float nf = __fmaf_rn(x, AOR_INVPI, AOR_SHIFT);
    unsigned odd = __float_as_uint(nf) << 31;
    float n = __fsub_rn(nf, AOR_SHIFT);
    float r = __fmaf_rn(-AOR_PI1, n, x);
    r = __fmaf_rn(-AOR_PI2, n, r);
    r = __fmaf_rn(-AOR_PI3, n, r);
    return aor_sin_core(r, odd);
}

__device__ __forceinline__ float aor_cosf(float x) {
    float r0 = fabsf(x);
    float nf = __fmaf_rn(r0, AOR_INVPI, 0.5f);
    float t  = __fadd_rn(nf, AOR_SHIFT);
    unsigned odd = __float_as_uint(t) << 31;
    float n = __fsub_rn(__fsub_rn(t, AOR_SHIFT), 0.5f);
    float r = __fmaf_rn(-AOR_PI1, n, r0);
    r = __fmaf_rn(-AOR_PI2, n, r);
    r = __fmaf_rn(-AOR_PI3, n, r);
    return aor_sin_core(r, odd);
}

// ---------------- K0: sin/cos table + weight transposes --------------------
__global__ void k_init(const float* __restrict__ W,
                       const float* __restrict__ Wr,
                       const float* __restrict__ Wi) {
    int i = blockIdx.x * blockDim.x + threadIdx.x;
    if (i < RESN) {
        float ang = __fmul_rn((float)i, ANG_F);
        g_tab[i] = make_float2(aor_sinf(ang), aor_cosf(ang));
    }
    int o = i - RESN;
    if (o >= 0 && o < LL*NN*DD) {
        int l = o >> 15, k = (o >> 8) & (DD-1), j = o & (NN-1);
        g_Wt[o] = W[l*32768 + j*DD + k];
    }
    int o2 = o - LL*NN*DD;
    if (o2 >= 0 && o2 < LL*NN*DD) {
        int l = o2 >> 15, j = (o2 >> 7) & (NN-1), d = o2 & (DD-1);
        g_Wrt[o2] = Wr[l*32768 + d*NN + j];
    }
    int o3 = o2 - LL*NN*DD;
    if (o3 >= 0 && o3 < LL*NN*DD) {
        int l = o3 >> 15, j = (o3 >> 7) & (NN-1), d = o3 & (DD-1);
        g_Wit[o3] = Wi[l*32768 + d*NN + j];
    }
}

// ---------------- K1: elementwise recurrence -> X0, final h ----------------
// VALIDATED in R6 (passed). Do not modify.
__global__ void k_recur(const int* __restrict__ ids,
                        const float* __restrict__ emb,
                        float* __restrict__ out) {
    __shared__ float2 stab[RESN];
    __shared__ int    sids[SS];
    const int b = blockIdx.x;     // 8 blocks
    const int d = threadIdx.x;    // 128 threads
    for (int i = threadIdx.x; i < RESN; i += 128) stab[i] = g_tab[i];
    for (int i = threadIdx.x; i < SS; i += 128)   sids[i] = ids[b*SS + i];
    __syncthreads();

    float hr = 0.f, hi = 0.f;
    int id0 = sids[0];
    float w  = emb[(size_t)id0*(2*DD) + d];
    float be = emb[(size_t)id0*(2*DD) + DD + d];

    for (int t = 0; t < SS; t++) {
        float wn = 0.f, bn = 0.f;
        if (t + 1 < SS) {
            int idn = sids[t+1];
            wn = emb[(size_t)idn*(2*DD) + d];
            bn = emb[(size_t)idn*(2*DD) + DD + d];
        }
        float div   = __fdiv_rn(__fadd_rn(hr, hi), __fadd_rn(1.0f, fabsf(w)));
        float tphi  = __fmul_rn((float)t, PHI_F);
        float theta = __fadd_rn(__fadd_rn(div, be), tphi);
        int ii = __float2int_rn(__fmul_rn(theta, CSC_F)) & (RESN - 1);
        float2 sc = stab[ii];
        hi = sc.x; hr = sc.y;
        g_X[(b*SS + t)*DD + d] = __fadd_rn(hr, hi);
        w = wn; be = bn;
    }
    out[HOFF + b*DD + d]           = hr;
    out[HOFF + BB*DD + b*DD + d]   = hi;
}

// ---------------- K2: fused 2-layer MLP over 2048 independent rows ---------
// Math identical to R6-validated version. Only change: the FINAL write-back
// stores tf32-rounded values (same cvt.rna k_gemm previously applied at
// staging) so k_gemm can copy A with cp.async, no conversion.
#define TM 8
__global__ __launch_bounds__(256) void k_mlp(const float* __restrict__ bvec) {
    __shared__ __align__(16) float xs[TM][DD];
    __shared__ __align__(16) float cs[TM][NN];
    __shared__ __align__(16) float sn[TM][NN];
    const int tid = threadIdx.x;
    const int r0  = blockIdx.x * TM;

    for (int i = tid; i < TM*DD; i += 256)
        xs[i >> 7][i & (DD-1)] = g_X[(r0 + (i >> 7))*DD + (i & (DD-1))];

    for (int l = 0; l < LL; l++) {
        __syncthreads();
        float acc[TM];
        #pragma unroll
        for (int r = 0; r < TM; r++) acc[r] = 0.f;
        const float* wt = g_Wt + l*DD*NN;
        #pragma unroll 2
        for (int k4 = 0; k4 < DD/4; k4++) {
            float4 xv[TM];
            #pragma unroll
            for (int r = 0; r < TM; r++)
                xv[r] = ((const float4*)xs[r])[k4];
            #pragma unroll
            for (int kk = 0; kk < 4; kk++) {
                float wv = wt[(k4*4 + kk)*NN + tid];
                #pragma unroll
                for (int r = 0; r < TM; r++) {
                    float x = (kk == 0) ? xv[r].x : (kk == 1) ? xv[r].y :
                              (kk == 2) ? xv[r].z : xv[r].w;
                    acc[r] += x * wv;
                }
            }
        }
        float bj = bvec[l*NN + tid];
        #pragma unroll
        for (int r = 0; r < TM; r++) {
            float tphi = (float)((r0 + r) & (SS-1)) * PHI_F;
            float th = (acc[r] + bj) + tphi;
            int ii = __float2int_rn(th * CSC_F) & (RESN - 1);
            float2 sc = g_tab[ii];
            sn[r][tid] = sc.x;
            cs[r][tid] = sc.y;
        }
        __syncthreads();
        const int dg = tid & 31;
        const int r  = tid >> 5;
        const float4* wr4 = (const float4*)(g_Wrt + l*NN*DD);
        const float4* wi4 = (const float4*)(g_Wit + l*NN*DD);
        float o0 = 0.f, o1 = 0.f, o2 = 0.f, o3 = 0.f;
        #pragma unroll 2
        for (int j4 = 0; j4 < NN/4; j4++) {
            float4 cv = ((const float4*)cs[r])[j4];
            float4 sv = ((const float4*)sn[r])[j4];
            #pragma unroll
            for (int jj = 0; jj < 4; jj++) {
                int j = j4*4 + jj;
                float4 a  = wr4[j*(DD/4) + dg];
                float4 b2 = wi4[j*(DD/4) + dg];
                float c = (jj == 0) ? cv.x : (jj == 1) ? cv.y : (jj == 2) ? cv.z : cv.w;
                float s = (jj == 0) ? sv.x : (jj == 1) ? sv.y : (jj == 2) ? sv.z : sv.w;
                o0 += c*a.x + s*b2.x;
                o1 += c*a.y + s*b2.y;
                o2 += c*a.z + s*b2.z;
                o3 += c*a.w + s*b2.w;
            }
        }
        int dbase = dg * 4;
        float ov[4] = {o0, o1, o2, o3};
        #pragma unroll
        for (int q = 0; q < 4; q++) {
            float o = ov[q];
            float sg = 1.0f / (1.0f + expf(-o));
            xs[r][dbase + q] += o * sg;
        }
    }
    __syncthreads();
    // write-back pre-rounded to tf32 (bit pattern is a valid f32)
    for (int i = tid; i < TM*DD; i += 256)
        g_X[(r0 + (i >> 7))*DD + (i & (DD-1))] =
            __uint_as_float(f2tf32(xs[i >> 7][i & (DD-1)]));
}

// ---------------- K3: logits GEMM (M=2048, N=50257, K=128), tf32 mma.sync --
// v4: 1 CTA/SM persistent (grid=148), 512 threads, CTA tile 128x128,
// double-buffered cp.async A staging (X pre-rounded to tf32 by k_mlp),
// B staged at nt boundaries, ldmatrix.x4 fragments, direct STG epilogue.
#define PA 132
#define ABUF_BYTES (128*PA*4)                    // 67584
#define K3_SMEM (3*ABUF_BYTES)                   // 202752 (A x2 + B)
#define K3_GRID 148
#define K3_ITEMS (393*16)                        // 6288

__device__ __forceinline__ void ldsm_x4(unsigned& r0, unsigned& r1,
                                        unsigned& r2, unsigned& r3, unsigned addr) {
    asm volatile("ldmatrix.sync.aligned.m8n8.x4.shared.b16 {%0,%1,%2,%3}, [%4];"
                 : "=r"(r0), "=r"(r1), "=r"(r2), "=r"(r3) : "r"(addr));
}

__global__ __launch_bounds__(512, 1) void k_gemm(const float* __restrict__ Bmat,
                                                 float* __restrict__ out) {
    extern __shared__ unsigned smemu[];
    unsigned* Bs = smemu + 2*128*PA;             // B after the two A buffers

    const int tid  = threadIdx.x;
    const int warp = tid >> 5, lane = tid & 31;
    const int grp  = lane >> 2, tig = lane & 3;
    const int wm   = (warp >> 2) * 32;           // 4 m-groups
    const int wn   = (warp & 3) * 32;            // 4 n-groups

    const unsigned sbase  = (unsigned)__cvta_generic_to_shared(smemu);
    const unsigned bs_u32 = sbase + 2u*ABUF_BYTES;

    // A fragment ldmatrix lane addressing (validated R8): x4 covers m16k8
    const unsigned aOffL = (unsigned)((wm + (lane & 15))*PA)*4u + (unsigned)(lane >> 4)*16u;
    // B x4: tiles (ni_even,k0),(ni_even,k1),(ni_odd,k0),(ni_odd,k1)
    const unsigned bOffL = (unsigned)((wn + ((lane >> 4) & 1)*8 + (lane & 7))*PA)*4u
                         + (unsigned)((lane >> 3) & 1)*16u;

    const int start = (int)(((long long)blockIdx.x       * K3_ITEMS) / K3_GRID);
    const int stop  = (int)(((long long)(blockIdx.x + 1) * K3_ITEMS) / K3_GRID);
    if (start >= stop) return;

    // prologue: async-prefetch A of first item into buffer 0
    {
        const float* src = g_X + (size_t)((start & 15) * 128) * DD;
        #pragma unroll
        for (int it = 0; it < 8; it++) {
            int c = tid + it*512;                // 4096 16B-chunks
            int r = c >> 5, k4 = c & 31;
            unsigned dst = sbase + (unsigned)(r*PA + k4*4)*4u;
            asm volatile("cp.async.cg.shared.global [%0], [%1], 16;"
                         :: "r"(dst), "l"(src + r*DD + k4*4));
        }
        asm volatile("cp.async.commit_group;" ::: "memory");
    }

    int cur = 0, cur_nt = -1;
    for (int item = start; item < stop; item++) {
        const int nt = item >> 4, mt = item & 15;
        const int n0 = nt * 128, m0 = mt * 128;

        asm volatile("cp.async.wait_group 0;" ::: "memory");
        __syncthreads();      // A[cur] visible to all; all done reading A[cur^1], Bs

        if (nt != cur_nt) {   // stage B (synchronous; ~3x per CTA)
            for (int i = tid; i < 128*32; i += 512) {
                int n = i >> 5, k4 = i & 31;
                unsigned* bp = Bs + n*PA + k4*4;
                if (n0 + n < VV) {
                    float4 v = ((const float4*)(Bmat + (size_t)(n0 + n)*DD))[k4];
                    bp[0] = f2tf32(v.x); bp[1] = f2tf32(v.y);
                    bp[2] = f2tf32(v.z); bp[3] = f2tf32(v.w);
                } else {
                    bp[0] = 0u; bp[1] = 0u; bp[2] = 0u; bp[3] = 0u;
                }
            }
            cur_nt = nt;
            __syncthreads();
        }

        if (item + 1 < stop) {   // prefetch next A into the other buffer
            const float* src = g_X + (size_t)(((item + 1) & 15) * 128) * DD;
            unsigned dbase = sbase + (unsigned)(cur ^ 1)*ABUF_BYTES;
            #pragma unroll
            for (int it = 0; it < 8; it++) {
                int c = tid + it*512;
                int r = c >> 5, k4 = c & 31;
                asm volatile("cp.async.cg.shared.global [%0], [%1], 16;"
                             :: "r"(dbase + (unsigned)(r*PA + k4*4)*4u),
                                "l"(src + r*DD + k4*4));
            }
            asm volatile("cp.async.commit_group;" ::: "memory");
        }

        // ---- compute from A[cur] ----
        const unsigned aBase = sbase + (unsigned)cur*ABUF_BYTES + aOffL;
        const unsigned bBase = bs_u32 + bOffL;

        float acc[2][4][4];
        #pragma unroll
        for (int mi = 0; mi < 2; mi++)
            #pragma unroll
            for (int ni = 0; ni < 4; ni++)
                #pragma unroll
                for (int q = 0; q < 4; q++) acc[mi][ni][q] = 0.f;

        #pragma unroll
        for (int kk = 0; kk < 16; kk++) {
            const unsigned koff = kk * 32u;
            unsigned a[2][4], b[2][4];
            ldsm_x4(a[0][0], a[0][1], a[0][2], a[0][3], aBase + koff);
            ldsm_x4(a[1][0], a[1][1], a[1][2], a[1][3], aBase + 16u*PA*4u + koff);
            ldsm_x4(b[0][0], b[0][1], b[0][2], b[0][3], bBase + koff);            // ni 0,1
            ldsm_x4(b[1][0], b[1][1], b[1][2], b[1][3], bBase + 16u*PA*4u + koff); // ni 2,3
            #pragma unroll
            for (int ni = 0; ni < 4; ni++) {
                unsigned b0 = b[ni >> 1][(ni & 1)*2];
                unsigned b1 = b[ni >> 1][(ni & 1)*2 + 1];
                #pragma unroll
                for (int mi = 0; mi < 2; mi++) {
                    asm volatile(
                        "mma.sync.aligned.m16n8k8.row.col.f32.tf32.tf32.f32 "
                        "{%0,%1,%2,%3}, {%4,%5,%6,%7}, {%8,%9}, {%0,%1,%2,%3};"
                        : "+f"(acc[mi][ni][0]), "+f"(acc[mi][ni][1]),
                          "+f"(acc[mi][ni][2]), "+f"(acc[mi][ni][3])
                        : "r"(a[mi][0]), "r"(a[mi][1]), "r"(a[mi][2]), "r"(a[mi][3]),
                          "r"(b0), "r"(b1));
                }
            }
        }

        // ---- epilogue: direct stores (VV odd => rows arbitrarily aligned) ----
        #pragma unroll
        for (int mi = 0; mi < 2; mi++) {
            #pragma unroll
            for (int ni = 0; ni < 4; ni++) {
                int rr  = wm + mi*16 + grp;
                int col = n0 + wn + ni*8 + 2*tig;
                float* p0 = out + (size_t)(m0 + rr)*VV + col;
                float* p1 = out + (size_t)(m0 + rr + 8)*VV + col;
                if (col + 1 < VV) {
                    p0[0] = acc[mi][ni][0]; p0[1] = acc[mi][ni][1];
                    p1[0] = acc[mi][ni][2]; p1[1] = acc[mi][ni][3];
                } else if (col < VV) {
                    p0[0] = acc[mi][ni][0];
                    p1[0] = acc[mi][ni][2];
                }
            }
        }
        cur ^= 1;
    }
}

// ---------------- launch ---------------------------------------------------
extern "C" void kernel_launch(void* const* d_in, const int* in_sizes, int n_in,
                              void* d_out, int out_size) {
    const int*   ids = (const int*)  d_in[0];
    const float* emb = (const float*)d_in[1];
    const float* W   = (const float*)d_in[2];
    const float* bv  = (const float*)d_in[3];
    const float* Wr  = (const float*)d_in[4];
    const float* Wi  = (const float*)d_in[5];
    const float* ow  = (const float*)d_in[6];
    float* out = (float*)d_out;

    (void)cudaFuncSetAttribute(k_gemm, cudaFuncAttributeMaxDynamicSharedMemorySize, K3_SMEM);

    k_init <<<784, 256>>>(W, Wr, Wi);      // 784*256 = 200704 = 4096 + 3*65536
    k_recur<<<BB, 128>>>(ids, emb, out);
    k_mlp  <<<MM/TM, 256>>>(bv);
    k_gemm <<<K3_GRID, 512, K3_SMEM>>>(ow, out);
}

// round 11
// speedup vs baseline: 1.0469x; 1.0469x over previous
#include <cuda_runtime.h>
#include <math.h>
#include <stdint.h>

#define VV 50257
#define DD 128
#define NN 256
#define LL 2
#define BB 8
#define SS 256
#define MM (BB*SS)          // 2048
#define RESN 4096
#define HOFF ((size_t)MM * VV)

#define PHI_F 1.6180339887498949f
#define CSC_F 651.8986469044033f          // RES / (2*pi)
#define ANG_F 0.0015339807878856412f      // 2*pi / RES

// ---------------- scratch (static device memory; no allocations) -----------
__device__ float2 g_tab[RESN];
__device__ float  g_X[MM * DD];          // post-MLP: holds tf32-rounded values
__device__ float  g_Wt [LL * DD * NN];   // [l][k][j]  (transposed layer_W)
__device__ float  g_Wrt[LL * NN * DD];   // [l][j][d]  (transposed layer_Wr)
__device__ float  g_Wit[LL * NN * DD];   // [l][j][d]  (transposed layer_Wi)

__device__ __forceinline__ unsigned f2tf32(float v) {
    unsigned u;
    asm("cvt.rna.tf32.f32 %0, %1;" : "=r"(u) : "f"(v));
    return u;
}

// ------- ARM optimized-routines AdvSIMD sinf/cosf (glibc libmvec) ----------
// VALIDATED in R6 (passed). Do not modify.
#define AOR_INVPI  0x1.45f306p-2f
#define AOR_PI1    0x1.921fb6p+1f
#define AOR_PI2   -0x1.777a5cp-24f
#define AOR_PI3   -0x1.ee59dap-49f
#define AOR_SHIFT  0x1.8p+23f
#define AOR_P0    -0x1.555548p-3f
#define AOR_P1     0x1.110df4p-7f
#define AOR_P2    -0x1.9f42eap-13f
#define AOR_P3     0x1.5b2e76p-19f

__device__ __forceinline__ float aor_sin_core(float r, unsigned odd) {
    float r2 = __fmul_rn(r, r);
    float y  = __fmaf_rn(AOR_P3, r2, AOR_P2);
    y = __fmaf_rn(y, r2, AOR_P1);
    y = __fmaf_rn(y, r2, AOR_P0);
    y = __fmaf_rn(__fmul_rn(y, r2), r, r);
    return __uint_as_float(__float_as_uint(y) ^ odd);
}

__device__ __forceinline__ float aor_sinf(float x) {
    float nf = __fmaf_rn(x, AOR_INVPI, AOR_SHIFT);
    unsigned odd = __float_as_uint(nf) << 31;
    float n = __fsub_rn(nf, AOR_SHIFT);
    float r = __fmaf_rn(-AOR_PI1, n, x);
    r = __fmaf_rn(-AOR_PI2, n, r);
    r = __fmaf_rn(-AOR_PI3, n, r);
    return aor_sin_core(r, odd);
}

__device__ __forceinline__ float aor_cosf(float x) {
    float r0 = fabsf(x);
    float nf = __fmaf_rn(r0, AOR_INVPI, 0.5f);
    float t  = __fadd_rn(nf, AOR_SHIFT);
    unsigned odd = __float_as_uint(t) << 31;
    float n = __fsub_rn(__fsub_rn(t, AOR_SHIFT), 0.5f);
    float r = __fmaf_rn(-AOR_PI1, n, r0);
    r = __fmaf_rn(-AOR_PI2, n, r);
    r = __fmaf_rn(-AOR_PI3, n, r);
    return aor_sin_core(r, odd);
}

// ---------------- K0: sin/cos table + weight transposes --------------------
__global__ void k_init(const float* __restrict__ W,
                       const float* __restrict__ Wr,
                       const float* __restrict__ Wi) {
    int i = blockIdx.x * blockDim.x + threadIdx.x;
    if (i < RESN) {
        float ang = __fmul_rn((float)i, ANG_F);
        g_tab[i] = make_float2(aor_sinf(ang), aor_cosf(ang));
    }
    int o = i - RESN;
    if (o >= 0 && o < LL*NN*DD) {
        int l = o >> 15, k = (o >> 8) & (DD-1), j = o & (NN-1);
        g_Wt[o] = W[l*32768 + j*DD + k];
    }
    int o2 = o - LL*NN*DD;
    if (o2 >= 0 && o2 < LL*NN*DD) {
        int l = o2 >> 15, j = (o2 >> 7) & (NN-1), d = o2 & (DD-1);
        g_Wrt[o2] = Wr[l*32768 + d*NN + j];
    }
    int o3 = o2 - LL*NN*DD;
    if (o3 >= 0 && o3 < LL*NN*DD) {
        int l = o3 >> 15, j = (o3 >> 7) & (NN-1), d = o3 & (DD-1);
        g_Wit[o3] = Wi[l*32768 + d*NN + j];
    }
}

// ---------------- K1: elementwise recurrence -> X0, final h ----------------
// VALIDATED in R6 (passed). Do not modify.
__global__ void k_recur(const int* __restrict__ ids,
                        const float* __restrict__ emb,
                        float* __restrict__ out) {
    __shared__ float2 stab[RESN];
    __shared__ int    sids[SS];
    const int b = blockIdx.x;     // 8 blocks
    const int d = threadIdx.x;    // 128 threads
    for (int i = threadIdx.x; i < RESN; i += 128) stab[i] = g_tab[i];
    for (int i = threadIdx.x; i < SS; i += 128)   sids[i] = ids[b*SS + i];
    __syncthreads();

    float hr = 0.f, hi = 0.f;
    int id0 = sids[0];
    float w  = emb[(size_t)id0*(2*DD) + d];
    float be = emb[(size_t)id0*(2*DD) + DD + d];

    for (int t = 0; t < SS; t++) {
        float wn = 0.f, bn = 0.f;
        if (t + 1 < SS) {
            int idn = sids[t+1];
            wn = emb[(size_t)idn*(2*DD) + d];
            bn = emb[(size_t)idn*(2*DD) + DD + d];
        }
        float div   = __fdiv_rn(__fadd_rn(hr, hi), __fadd_rn(1.0f, fabsf(w)));
        float tphi  = __fmul_rn((float)t, PHI_F);
        float theta = __fadd_rn(__fadd_rn(div, be), tphi);
        int ii = __float2int_rn(__fmul_rn(theta, CSC_F)) & (RESN - 1);
        float2 sc = stab[ii];
        hi = sc.x; hr = sc.y;
        g_X[(b*SS + t)*DD + d] = __fadd_rn(hr, hi);
        w = wn; be = bn;
    }
    out[HOFF + b*DD + d]           = hr;
    out[HOFF + BB*DD + b*DD + d]   = hi;
}

// ---------------- K2: fused 2-layer MLP over 2048 independent rows ---------
// VALIDATED (R9 passed, incl. tf32 pre-rounded write-back). Do not modify.
#define TM 8
__global__ __launch_bounds__(256) void k_mlp(const float* __restrict__ bvec) {
    __shared__ __align__(16) float xs[TM][DD];
    __shared__ __align__(16) float cs[TM][NN];
    __shared__ __align__(16) float sn[TM][NN];
    const int tid = threadIdx.x;
    const int r0  = blockIdx.x * TM;

    for (int i = tid; i < TM*DD; i += 256)
        xs[i >> 7][i & (DD-1)] = g_X[(r0 + (i >> 7))*DD + (i & (DD-1))];

    for (int l = 0; l < LL; l++) {
        __syncthreads();
        float acc[TM];
        #pragma unroll
        for (int r = 0; r < TM; r++) acc[r] = 0.f;
        const float* wt = g_Wt + l*DD*NN;
        #pragma unroll 2
        for (int k4 = 0; k4 < DD/4; k4++) {
            float4 xv[TM];
            #pragma unroll
            for (int r = 0; r < TM; r++)
                xv[r] = ((const float4*)xs[r])[k4];
            #pragma unroll
            for (int kk = 0; kk < 4; kk++) {
                float wv = wt[(k4*4 + kk)*NN + tid];
                #pragma unroll
                for (int r = 0; r < TM; r++) {
                    float x = (kk == 0) ? xv[r].x : (kk == 1) ? xv[r].y :
                              (kk == 2) ? xv[r].z : xv[r].w;
                    acc[r] += x * wv;
                }
            }
        }
        float bj = bvec[l*NN + tid];
        #pragma unroll
        for (int r = 0; r < TM; r++) {
            float tphi = (float)((r0 + r) & (SS-1)) * PHI_F;
            float th = (acc[r] + bj) + tphi;
            int ii = __float2int_rn(th * CSC_F) & (RESN - 1);
            float2 sc = g_tab[ii];
            sn[r][tid] = sc.x;
            cs[r][tid] = sc.y;
        }
        __syncthreads();
        const int dg = tid & 31;
        const int r  = tid >> 5;
        const float4* wr4 = (const float4*)(g_Wrt + l*NN*DD);
        const float4* wi4 = (const float4*)(g_Wit + l*NN*DD);
        float o0 = 0.f, o1 = 0.f, o2 = 0.f, o3 = 0.f;
        #pragma unroll 2
        for (int j4 = 0; j4 < NN/4; j4++) {
            float4 cv = ((const float4*)cs[r])[j4];
            float4 sv = ((const float4*)sn[r])[j4];
            #pragma unroll
            for (int jj = 0; jj < 4; jj++) {
                int j = j4*4 + jj;
                float4 a  = wr4[j*(DD/4) + dg];
                float4 b2 = wi4[j*(DD/4) + dg];
                float c = (jj == 0) ? cv.x : (jj == 1) ? cv.y : (jj == 2) ? cv.z : cv.w;
                float s = (jj == 0) ? sv.x : (jj == 1) ? sv.y : (jj == 2) ? sv.z : sv.w;
                o0 += c*a.x + s*b2.x;
                o1 += c*a.y + s*b2.y;
                o2 += c*a.z + s*b2.z;
                o3 += c*a.w + s*b2.w;
            }
        }
        int dbase = dg * 4;
        float ov[4] = {o0, o1, o2, o3};
        #pragma unroll
        for (int q = 0; q < 4; q++) {
            float o = ov[q];
            float sg = 1.0f / (1.0f + expf(-o));
            xs[r][dbase + q] += o * sg;
        }
    }
    __syncthreads();
    // write-back pre-rounded to tf32 (bit pattern is a valid f32)
    for (int i = tid; i < TM*DD; i += 256)
        g_X[(r0 + (i >> 7))*DD + (i & (DD-1))] =
            __uint_as_float(f2tf32(xs[i >> 7][i & (DD-1)]));
}

// ---------------- K3: logits GEMM (M=2048, N=50257, K=128), tf32 mma.sync --
// v5: persistent 148 CTAs x 256 thr (8 warps, one small barrier domain),
// CTA item 128x128, warp tile 32x64 (24 B/out fragment traffic vs 32),
// compact 16B-XOR-swizzled smem (rows 512B; chunk ^= row&7 -> LDSM
// conflict-free), double-buffered cp.async A staging (X pre-rounded tf32),
// B staged at nt boundaries. Fragment lane maps validated in R8/R9.
#define ABUF 65536                           // 128 rows x 512 B
#define K3_SMEM (3*ABUF)                     // 196608: A x2 + B
#define K3_GRID 148
#define NTT 393                              // ceil(50257/128)
#define K3_ITEMS (NTT*16)                    // 6288

__device__ __forceinline__ void ldsm_x4(unsigned& r0, unsigned& r1,
                                        unsigned& r2, unsigned& r3, unsigned addr) {
    asm volatile("ldmatrix.sync.aligned.m8n8.x4.shared.b16 {%0,%1,%2,%3}, [%4];"
                 : "=r"(r0), "=r"(r1), "=r"(r2), "=r"(r3) : "r"(addr));
}

__global__ __launch_bounds__(256, 1) void k_gemm(const float* __restrict__ Bmat,
                                                 float* __restrict__ out) {
    extern __shared__ __align__(16) char smem[];
    const unsigned sbase = (unsigned)__cvta_generic_to_shared(smem);
    const unsigned bbase = sbase + 2u*ABUF;

    const int tid  = threadIdx.x;
    const int warp = tid >> 5, lane = tid & 31;
    const int grp  = lane >> 2, tig = lane & 3;
    const int wm   = (warp >> 1) * 32;       // 4 m-groups: 0,32,64,96
    const int wn   = (warp & 1) * 64;        // 2 n-groups: 0,64

    // fragment lane constants (R8/R9-validated maps, compact layout)
    const int rA  = wm + (lane & 15);                    // A row, mi adds 16
    const int hiA = lane >> 4;                           // 16B half of k-step
    const int r7A = rA & 7;                              // same for mi=1 (16%8=0)
    const int rB  = wn + ((lane >> 4) & 1)*8 + (lane & 7); // B row (n), nb adds 16
    const int hiB = (lane >> 3) & 1;
    const int r7B = rB & 7;

    const int start = (int)(((long long)blockIdx.x       * K3_ITEMS) / K3_GRID);
    const int stop  = (int)(((long long)(blockIdx.x + 1) * K3_ITEMS) / K3_GRID);
    if (start >= stop) return;

    // prologue: async-prefetch A of first item into buffer 0
    {
        const float* src = g_X + (size_t)((start & 15) * 128) * DD;
        #pragma unroll
        for (int it = 0; it < 16; it++) {
            int c = tid + it*256;                    // 4096 16B chunks
            int r = c >> 5, k4 = c & 31;
            unsigned dst = sbase + (unsigned)(r*512 + ((k4 ^ (r & 7)) << 4));
            asm volatile("cp.async.cg.shared.global [%0], [%1], 16;"
                         :: "r"(dst), "l"(src + r*DD + k4*4));
        }
        asm volatile("cp.async.commit_group;" ::: "memory");
    }

    int cur = 0, cur_nt = -1;
    for (int item = start; item < stop; item++) {
        const int nt = item >> 4, mt = item & 15;
        const int n0 = nt * 128, m0 = mt * 128;

        asm volatile("cp.async.wait_group 0;" ::: "memory");
        __syncthreads();      // A[cur] visible; all reads of A[cur^1]/Bs done

        if (nt != cur_nt) {   // stage B (synchronous; ~3x per CTA)
            for (int i = tid; i < 128*32; i += 256) {
                int r = i >> 5, k4 = i & 31;
                unsigned boff = (unsigned)(r*512 + ((k4 ^ (r & 7)) << 4));
                uint4 dv;
                if (n0 + r < VV) {
                    float4 v = ((const float4*)(Bmat + (size_t)(n0 + r)*DD))[k4];
                    dv.x = f2tf32(v.x); dv.y = f2tf32(v.y);
                    dv.z = f2tf32(v.z); dv.w = f2tf32(v.w);
                } else {
                    dv.x = dv.y = dv.z = dv.w = 0u;
                }
                *(uint4*)(smem + 2*ABUF + boff) = dv;
            }
            cur_nt = nt;
            __syncthreads();
        }

        if (item + 1 < stop) {   // prefetch next A into the other buffer
            const float* src = g_X + (size_t)(((item + 1) & 15) * 128) * DD;
            unsigned dbase = sbase + (unsigned)(cur ^ 1)*ABUF;
            #pragma unroll
            for (int it = 0; it < 16; it++) {
                int c = tid + it*256;
                int r = c >> 5, k4 = c & 31;
                asm volatile("cp.async.cg.shared.global [%0], [%1], 16;"
                             :: "r"(dbase + (unsigned)(r*512 + ((k4 ^ (r & 7)) << 4))),
                                "l"(src + r*DD + k4*4));
            }
            asm volatile("cp.async.commit_group;" ::: "memory");
        }

        // ---- compute from A[cur]: warp tile 32x64, 16 k-steps ----
        const unsigned aRow0 = sbase + (unsigned)cur*ABUF + (unsigned)(rA*512);
        const unsigned aRow1 = aRow0 + 16u*512u;
        const unsigned bRow0 = bbase + (unsigned)(rB*512);

        float acc[2][8][4];
        #pragma unroll
        for (int mi = 0; mi < 2; mi++)
            #pragma unroll
            for (int ni = 0; ni < 8; ni++)
                #pragma unroll
                for (int q = 0; q < 4; q++) acc[mi][ni][q] = 0.f;

        #pragma unroll
        for (int kk = 0; kk < 16; kk++) {
            const unsigned cA = (unsigned)(((kk*2 + hiA) ^ r7A) << 4);
            const unsigned cB = (unsigned)(((kk*2 + hiB) ^ r7B) << 4);
            unsigned a[2][4], b[4][4];
            ldsm_x4(a[0][0], a[0][1], a[0][2], a[0][3], aRow0 + cA);
            ldsm_x4(a[1][0], a[1][1], a[1][2], a[1][3], aRow1 + cA);
            #pragma unroll
            for (int nb = 0; nb < 4; nb++)
                ldsm_x4(b[nb][0], b[nb][1], b[nb][2], b[nb][3],
                        bRow0 + (unsigned)nb*(16u*512u) + cB);
            #pragma unroll
            for (int ni = 0; ni < 8; ni++) {
                unsigned b0 = b[ni >> 1][(ni & 1)*2];
                unsigned b1 = b[ni >> 1][(ni & 1)*2 + 1];
                #pragma unroll
                for (int mi = 0; mi < 2; mi++) {
                    asm volatile(
                        "mma.sync.aligned.m16n8k8.row.col.f32.tf32.tf32.f32 "
                        "{%0,%1,%2,%3}, {%4,%5,%6,%7}, {%8,%9}, {%0,%1,%2,%3};"
                        : "+f"(acc[mi][ni][0]), "+f"(acc[mi][ni][1]),
                          "+f"(acc[mi][ni][2]), "+f"(acc[mi][ni][3])
                        : "r"(a[mi][0]), "r"(a[mi][1]), "r"(a[mi][2]), "r"(a[mi][3]),
                          "r"(b0), "r"(b1));
                }
            }
        }

        // ---- epilogue: direct stores (VV odd => rows arbitrarily aligned) ----
        #pragma unroll
        for (int mi = 0; mi < 2; mi++) {
            #pragma unroll
            for (int ni = 0; ni < 8; ni++) {
                int rr  = wm + mi*16 + grp;
                int col = n0 + wn + ni*8 + 2*tig;
                float* p0 = out + (size_t)(m0 + rr)*VV + col;
                float* p1 = out + (size_t)(m0 + rr + 8)*VV + col;
                if (col + 1 < VV) {
                    p0[0] = acc[mi][ni][0]; p0[1] = acc[mi][ni][1];
                    p1[0] = acc[mi][ni][2]; p1[1] = acc[mi][ni][3];
                } else if (col < VV) {
                    p0[0] = acc[mi][ni][0];
                    p1[0] = acc[mi][ni][2];
                }
            }
        }
        cur ^= 1;
    }
}

// ---------------- launch ---------------------------------------------------
extern "C" void kernel_launch(void* const* d_in, const int* in_sizes, int n_in,
                              void* d_out, int out_size) {
    const int*   ids = (const int*)  d_in[0];
    const float* emb = (const float*)d_in[1];
    const float* W   = (const float*)d_in[2];
    const float* bv  = (const float*)d_in[3];
    const float* Wr  = (const float*)d_in[4];
    const float* Wi  = (const float*)d_in[5];
    const float* ow  = (const float*)d_in[6];
    float* out = (float*)d_out;

    (void)cudaFuncSetAttribute(k_gemm, cudaFuncAttributeMaxDynamicSharedMemorySize, K3_SMEM);

    k_init <<<784, 256>>>(W, Wr, Wi);      // 784*256 = 200704 = 4096 + 3*65536
    k_recur<<<BB, 128>>>(ids, emb, out);
    k_mlp  <<<MM/TM, 256>>>(bv);
    k_gemm <<<K3_GRID, 256, K3_SMEM>>>(ow, out);
}

// round 13
// speedup vs baseline: 1.3148x; 1.2559x over previous
#include <cuda_runtime.h>
#include <math.h>
#include <stdint.h>

#define VV 50257
#define DD 128
#define NN 256
#define LL 2
#define BB 8
#define SS 256
#define MM (BB*SS)          // 2048
#define RESN 4096
#define HOFF ((size_t)MM * VV)

#define PHI_F 1.6180339887498949f
#define CSC_F 651.8986469044033f          // RES / (2*pi)
#define ANG_F 0.0015339807878856412f      // 2*pi / RES

#define NTT 393                           // ceil(50257/128)
#define VPAD (NTT*128)                    // 50304 padded vocab rows

// ---------------- scratch (static device memory; no allocations) -----------
__device__ float2 g_tab[RESN];
__device__ float  g_X[MM * DD];          // post-MLP: holds tf32-rounded values
__device__ float  g_Bt[(size_t)VPAD * DD]; // out_w pre-rounded to tf32, zero-padded
__device__ float  g_Wt [LL * DD * NN];   // [l][k][j]  (transposed layer_W)
__device__ float  g_Wrt[LL * NN * DD];   // [l][j][d]  (transposed layer_Wr)
__device__ float  g_Wit[LL * NN * DD];   // [l][j][d]  (transposed layer_Wi)

__device__ __forceinline__ unsigned f2tf32(float v) {
    unsigned u;
    asm("cvt.rna.tf32.f32 %0, %1;" : "=r"(u) : "f"(v));
    return u;
}

// ------- ARM optimized-routines AdvSIMD sinf/cosf (glibc libmvec) ----------
// VALIDATED in R6 (passed). Do not modify.
#define AOR_INVPI  0x1.45f306p-2f
#define AOR_PI1    0x1.921fb6p+1f
#define AOR_PI2   -0x1.777a5cp-24f
#define AOR_PI3   -0x1.ee59dap-49f
#define AOR_SHIFT  0x1.8p+23f
#define AOR_P0    -0x1.555548p-3f
#define AOR_P1     0x1.110df4p-7f
#define AOR_P2    -0x1.9f42eap-13f
#define AOR_P3     0x1.5b2e76p-19f

__device__ __forceinline__ float aor_sin_core(float r, unsigned odd) {
    float r2 = __fmul_rn(r, r);
    float y  = __fmaf_rn(AOR_P3, r2, AOR_P2);
    y = __fmaf_rn(y, r2, AOR_P1);
    y = __fmaf_rn(y, r2, AOR_P0);
    y = __fmaf_rn(__fmul_rn(y, r2), r, r);
    return __uint_as_float(__float_as_uint(y) ^ odd);
}

__device__ __forceinline__ float aor_sinf(float x) {
    float nf = __fmaf_rn(x, AOR_INVPI, AOR_SHIFT);
    unsigned odd = __float_as_uint(nf) << 31;
    float n = __fsub_rn(nf, AOR_SHIFT);
    float r = __fmaf_rn(-AOR_PI1, n, x);
    r = __fmaf_rn(-AOR_PI2, n, r);
    r = __fmaf_rn(-AOR_PI3, n, r);
    return aor_sin_core(r, odd);
}

__device__ __forceinline__ float aor_cosf(float x) {
    float r0 = fabsf(x);
    float nf = __fmaf_rn(r0, AOR_INVPI, 0.5f);
    float t  = __fadd_rn(nf, AOR_SHIFT);
    unsigned odd = __float_as_uint(t) << 31;
    float n = __fsub_rn(__fsub_rn(t, AOR_SHIFT), 0.5f);
    float r = __fmaf_rn(-AOR_PI1, n, r0);
    r = __fmaf_rn(-AOR_PI2, n, r);
    r = __fmaf_rn(-AOR_PI3, n, r);
    return aor_sin_core(r, odd);
}

// ---------------- K0: table + weight transposes + out_w tf32 copy ----------
__global__ void k_init(const float* __restrict__ W,
                       const float* __restrict__ Wr,
                       const float* __restrict__ Wi,
                       const float* __restrict__ OW) {
    int i = blockIdx.x * blockDim.x + threadIdx.x;
    if (i < RESN) {
        float ang = __fmul_rn((float)i, ANG_F);
        g_tab[i] = make_float2(aor_sinf(ang), aor_cosf(ang));
    }
    int o = i - RESN;
    if (o >= 0 && o < LL*NN*DD) {
        int l = o >> 15, k = (o >> 8) & (DD-1), j = o & (NN-1);
        g_Wt[o] = W[l*32768 + j*DD + k];
    }
    int o2 = o - LL*NN*DD;
    if (o2 >= 0 && o2 < LL*NN*DD) {
        int l = o2 >> 15, j = (o2 >> 7) & (NN-1), d = o2 & (DD-1);
        g_Wrt[o2] = Wr[l*32768 + d*NN + j];
    }
    int o3 = o2 - LL*NN*DD;
    if (o3 >= 0 && o3 < LL*NN*DD) {
        int l = o3 >> 15, j = (o3 >> 7) & (NN-1), d = o3 & (DD-1);
        g_Wit[o3] = Wi[l*32768 + d*NN + j];
    }
    // out_w -> g_Bt (tf32 bits), zero-pad rows [VV, VPAD)
    const int NCH = VPAD * (DD/4);              // float4 chunks
    for (int c = i; c < NCH; c += 784*256) {
        int row = c >> 5, k4 = c & 31;
        float4 dv;
        if (row < VV) {
            float4 v = ((const float4*)(OW + (size_t)row*DD))[k4];
            dv.x = __uint_as_float(f2tf32(v.x));
            dv.y = __uint_as_float(f2tf32(v.y));
            dv.z = __uint_as_float(f2tf32(v.z));
            dv.w = __uint_as_float(f2tf32(v.w));
        } else {
            dv.x = dv.y = dv.z = dv.w = 0.f;
        }
        ((float4*)(g_Bt + (size_t)row*DD))[k4] = dv;
    }
}

// ---------------- K1: elementwise recurrence -> X0, final h ----------------
// VALIDATED in R6 (passed). Do not modify.
__global__ void k_recur(const int* __restrict__ ids,
                        const float* __restrict__ emb,
                        float* __restrict__ out) {
    __shared__ float2 stab[RESN];
    __shared__ int    sids[SS];
    const int b = blockIdx.x;     // 8 blocks
    const int d = threadIdx.x;    // 128 threads
    for (int i = threadIdx.x; i < RESN; i += 128) stab[i] = g_tab[i];
    for (int i = threadIdx.x; i < SS; i += 128)   sids[i] = ids[b*SS + i];
    __syncthreads();

    float hr = 0.f, hi = 0.f;
    int id0 = sids[0];
    float w  = emb[(size_t)id0*(2*DD) + d];
    float be = emb[(size_t)id0*(2*DD) + DD + d];

    for (int t = 0; t < SS; t++) {
        float wn = 0.f, bn = 0.f;
        if (t + 1 < SS) {
            int idn = sids[t+1];
            wn = emb[(size_t)idn*(2*DD) + d];
            bn = emb[(size_t)idn*(2*DD) + DD + d];
        }
        float div   = __fdiv_rn(__fadd_rn(hr, hi), __fadd_rn(1.0f, fabsf(w)));
        float tphi  = __fmul_rn((float)t, PHI_F);
        float theta = __fadd_rn(__fadd_rn(div, be), tphi);
        int ii = __float2int_rn(__fmul_rn(theta, CSC_F)) & (RESN - 1);
        float2 sc = stab[ii];
        hi = sc.x; hr = sc.y;
        g_X[(b*SS + t)*DD + d] = __fadd_rn(hr, hi);
        w = wn; be = bn;
    }
    out[HOFF + b*DD + d]           = hr;
    out[HOFF + BB*DD + b*DD + d]   = hi;
}

// ---------------- K2: fused 2-layer MLP over 2048 independent rows ---------
// VALIDATED (R9 passed, incl. tf32 pre-rounded write-back). Do not modify.
#define TM 8
__global__ __launch_bounds__(256) void k_mlp(const float* __restrict__ bvec) {
    __shared__ __align__(16) float xs[TM][DD];
    __shared__ __align__(16) float cs[TM][NN];
    __shared__ __align__(16) float sn[TM][NN];
    const int tid = threadIdx.x;
    const int r0  = blockIdx.x * TM;

    for (int i = tid; i < TM*DD; i += 256)
        xs[i >> 7][i & (DD-1)] = g_X[(r0 + (i >> 7))*DD + (i & (DD-1))];

    for (int l = 0; l < LL; l++) {
        __syncthreads();
        float acc[TM];
        #pragma unroll
        for (int r = 0; r < TM; r++) acc[r] = 0.f;
        const float* wt = g_Wt + l*DD*NN;
        #pragma unroll 2
        for (int k4 = 0; k4 < DD/4; k4++) {
            float4 xv[TM];
            #pragma unroll
            for (int r = 0; r < TM; r++)
                xv[r] = ((const float4*)xs[r])[k4];
            #pragma unroll
            for (int kk = 0; kk < 4; kk++) {
                float wv = wt[(k4*4 + kk)*NN + tid];
                #pragma unroll
                for (int r = 0; r < TM; r++) {
                    float x = (kk == 0) ? xv[r].x : (kk == 1) ? xv[r].y :
                              (kk == 2) ? xv[r].z : xv[r].w;
                    acc[r] += x * wv;
                }
            }
        }
        float bj = bvec[l*NN + tid];
        #pragma unroll
        for (int r = 0; r < TM; r++) {
            float tphi = (float)((r0 + r) & (SS-1)) * PHI_F;
            float th = (acc[r] + bj) + tphi;
            int ii = __float2int_rn(th * CSC_F) & (RESN - 1);
            float2 sc = g_tab[ii];
            sn[r][tid] = sc.x;
            cs[r][tid] = sc.y;
        }
        __syncthreads();
        const int dg = tid & 31;
        const int r  = tid >> 5;
        const float4* wr4 = (const float4*)(g_Wrt + l*NN*DD);
        const float4* wi4 = (const float4*)(g_Wit + l*NN*DD);
        float o0 = 0.f, o1 = 0.f, o2 = 0.f, o3 = 0.f;
        #pragma unroll 2
        for (int j4 = 0; j4 < NN/4; j4++) {
            float4 cv = ((const float4*)cs[r])[j4];
            float4 sv = ((const float4*)sn[r])[j4];
            #pragma unroll
            for (int jj = 0; jj < 4; jj++) {
                int j = j4*4 + jj;
                float4 a  = wr4[j*(DD/4) + dg];
                float4 b2 = wi4[j*(DD/4) + dg];
                float c = (jj == 0) ? cv.x : (jj == 1) ? cv.y : (jj == 2) ? cv.z : cv.w;
                float s = (jj == 0) ? sv.x : (jj == 1) ? sv.y : (jj == 2) ? sv.z : sv.w;
                o0 += c*a.x + s*b2.x;
                o1 += c*a.y + s*b2.y;
                o2 += c*a.z + s*b2.z;
                o3 += c*a.w + s*b2.w;
            }
        }
        int dbase = dg * 4;
        float ov[4] = {o0, o1, o2, o3};
        #pragma unroll
        for (int q = 0; q < 4; q++) {
            float o = ov[q];
            float sg = 1.0f / (1.0f + expf(-o));
            xs[r][dbase + q] += o * sg;
        }
    }
    __syncthreads();
    // write-back pre-rounded to tf32 (bit pattern is a valid f32)
    for (int i = tid; i < TM*DD; i += 256)
        g_X[(r0 + (i >> 7))*DD + (i & (DD-1))] =
            __uint_as_float(f2tf32(xs[i >> 7][i & (DD-1)]));
}

// ---------------- K3: logits GEMM (M=2048, N=50257, K=128), tf32 mma.sync --
// v6: R8 skeleton (2 CTA/SM, 296 persistent CTAs, 64x128 items, 32x32 warp
// tiles, validated ldmatrix maps) + cp.async pure-copy staging (A from g_X,
// B from pre-converted g_Bt) + SMEM-STAGED EPILOGUE (Os aliases As; scattered
// acc stores hit smem, global stores are row-coalesced -> ~5x fewer L1 wf).
#define PA 132
#define K3_SMEM ((64*PA + 128*PA)*4)     // 101376 B -> 2 CTAs/SM
#define K3_GRID 296
#define K3_ITEMS (NTT*32)                // 12576 (393 nt x 32 m-chunks of 64)

__device__ __forceinline__ void ldsm_x4(unsigned& r0, unsigned& r1,
                                        unsigned& r2, unsigned& r3, unsigned addr) {
    asm volatile("ldmatrix.sync.aligned.m8n8.x4.shared.b16 {%0,%1,%2,%3}, [%4];"
                 : "=r"(r0), "=r"(r1), "=r"(r2), "=r"(r3) : "r"(addr));
}
__device__ __forceinline__ void cpa16(unsigned dst, const float* src) {
    asm volatile("cp.async.cg.shared.global [%0], [%1], 16;"
                 :: "r"(dst), "l"(src));
}

__global__ __launch_bounds__(256, 2) void k_gemm(const float* __restrict__ Bmat,
                                                 float* __restrict__ out) {
    extern __shared__ unsigned smemu[];
    float* Os = (float*)smemu;               // 64 x 129 floats, aliases As region

    const int tid  = threadIdx.x;
    const int warp = tid >> 5, lane = tid & 31;
    const int grp  = lane >> 2, tig = lane & 3;
    const int wm   = (warp >> 2) * 32;       // warp row base (0 or 32)
    const int wn   = (warp & 3) * 32;        // warp col base (0,32,64,96)

    const unsigned sbase  = (unsigned)__cvta_generic_to_shared(smemu);
    const unsigned bs_u32 = sbase + 64u*PA*4u;

    // validated ldmatrix lane addressing (R8/R9)
    const unsigned aBase = sbase + (unsigned)((wm + (lane & 15))*PA)*4u
                                 + (unsigned)(lane >> 4)*16u;
    const unsigned bBase = bs_u32 + (unsigned)((wn + ((lane >> 4) & 1)*8 + (lane & 7))*PA)*4u
                                  + (unsigned)((lane >> 3) & 1)*16u;

    const int start = (int)(((long long)blockIdx.x       * K3_ITEMS) / K3_GRID);
    const int stop  = (int)(((long long)(blockIdx.x + 1) * K3_ITEMS) / K3_GRID);
    if (start >= stop) return;

    // prologue: async copy A of first item (pure copy: g_X already tf32)
    {
        const float* src = g_X + (size_t)((start & 31) * 64) * DD;
        #pragma unroll
        for (int it = 0; it < 8; it++) {
            int c = tid + it*256;                // 2048 16B chunks (64 rows)
            int r = c >> 5, k4 = c & 31;
            cpa16(sbase + (unsigned)(r*PA + k4*4)*4u, src + r*DD + k4*4);
        }
        asm volatile("cp.async.commit_group;" ::: "memory");
    }

    int cur_nt = -1;
    for (int item = start; item < stop; item++) {
        const int nt = item >> 5, mc = item & 31;
        const int n0 = nt * 128, m0 = mc * 64;

        asm volatile("cp.async.wait_group 0;" ::: "memory");
        __syncthreads();      // A visible to all

        if (nt != cur_nt) {   // stage B: pure async copy from padded g_Bt
            #pragma unroll
            for (int it = 0; it < 16; it++) {
                int c = tid + it*256;            // 4096 chunks (128 rows)
                int r = c >> 5, k4 = c & 31;
                cpa16(bs_u32 + (unsigned)(r*PA + k4*4)*4u,
                      g_Bt + (size_t)(n0 + r)*DD + k4*4);
            }
            asm volatile("cp.async.commit_group;" ::: "memory");
            asm volatile("cp.async.wait_group 0;" ::: "memory");
            cur_nt = nt;
            __syncthreads();
        }

        // ---- compute: 16 k-steps, warp tile 32x32 ----
        float acc[2][4][4];
        #pragma unroll
        for (int mi = 0; mi < 2; mi++)
            #pragma unroll
            for (int ni = 0; ni < 4; ni++)
                #pragma unroll
                for (int q = 0; q < 4; q++) acc[mi][ni][q] = 0.f;

        #pragma unroll
        for (int kk = 0; kk < 16; kk++) {
            const unsigned koff = kk * 32u;
            unsigned a[2][4], b[2][4];
            ldsm_x4(a[0][0], a[0][1], a[0][2], a[0][3], aBase + koff);
            ldsm_x4(a[1][0], a[1][1], a[1][2], a[1][3], aBase + 16u*PA*4u + koff);
            ldsm_x4(b[0][0], b[0][1], b[0][2], b[0][3], bBase + koff);
            ldsm_x4(b[1][0], b[1][1], b[1][2], b[1][3], bBase + 16u*PA*4u + koff);
            #pragma unroll
            for (int ni = 0; ni < 4; ni++) {
                unsigned b0 = b[ni >> 1][(ni & 1)*2];
                unsigned b1 = b[ni >> 1][(ni & 1)*2 + 1];
                #pragma unroll
                for (int mi = 0; mi < 2; mi++) {
                    asm volatile(
                        "mma.sync.aligned.m16n8k8.row.col.f32.tf32.tf32.f32 "
                        "{%0,%1,%2,%3}, {%4,%5,%6,%7}, {%8,%9}, {%0,%1,%2,%3};"
                        : "+f"(acc[mi][ni][0]), "+f"(acc[mi][ni][1]),
                          "+f"(acc[mi][ni][2]), "+f"(acc[mi][ni][3])
                        : "r"(a[mi][0]), "r"(a[mi][1]), "r"(a[mi][2]), "r"(a[mi][3]),
                          "r"(b0), "r"(b1));
                }
            }
        }
        __syncthreads();      // all LDSM reads of As done (Os aliases As)

        // ---- staged epilogue: acc -> Os (smem) ----
        #pragma unroll
        for (int mi = 0; mi < 2; mi++) {
            #pragma unroll
            for (int ni = 0; ni < 4; ni++) {
                int rr = wm + mi*16 + grp;
                int cc = wn + ni*8 + 2*tig;
                Os[rr*129 + cc]       = acc[mi][ni][0];
                Os[rr*129 + cc + 1]   = acc[mi][ni][1];
                Os[(rr+8)*129 + cc]   = acc[mi][ni][2];
                Os[(rr+8)*129 + cc+1] = acc[mi][ni][3];
            }
        }
        __syncthreads();

        // ---- row-coalesced global stores ----
        #pragma unroll 4
        for (int i = tid; i < 64*128; i += 256) {
            int r = i >> 7, c = i & 127;
            int col = n0 + c;
            if (col < VV)
                out[(size_t)(m0 + r)*VV + col] = Os[r*129 + c];
        }
        __syncthreads();      // Os reads done before next A overwrites region

        if (item + 1 < stop) {   // async copy next A
            const float* src = g_X + (size_t)(((item + 1) & 31) * 64) * DD;
            #pragma unroll
            for (int it = 0; it < 8; it++) {
                int c = tid + it*256;
                int r = c >> 5, k4 = c & 31;
                cpa16(sbase + (unsigned)(r*PA + k4*4)*4u, src + r*DD + k4*4);
            }
            asm volatile("cp.async.commit_group;" ::: "memory");
        }
    }
}

// ---------------- launch ---------------------------------------------------
extern "C" void kernel_launch(void* const* d_in, const int* in_sizes, int n_in,
                              void* d_out, int out_size) {
    const int*   ids = (const int*)  d_in[0];
    const float* emb = (const float*)d_in[1];
    const float* W   = (const float*)d_in[2];
    const float* bv  = (const float*)d_in[3];
    const float* Wr  = (const float*)d_in[4];
    const float* Wi  = (const float*)d_in[5];
    const float* ow  = (const float*)d_in[6];
    float* out = (float*)d_out;

    (void)cudaFuncSetAttribute(k_gemm, cudaFuncAttributeMaxDynamicSharedMemorySize, K3_SMEM);

    k_init <<<784, 256>>>(W, Wr, Wi, ow);
    k_recur<<<BB, 128>>>(ids, emb, out);
    k_mlp  <<<MM/TM, 256>>>(bv);
    k_gemm <<<K3_GRID, 256, K3_SMEM>>>(ow, out);
}

// round 14
// speedup vs baseline: 1.4982x; 1.1395x over previous
#include <cuda_runtime.h>
#include <math.h>
#include <stdint.h>

#define VV 50257
#define DD 128
#define NN 256
#define LL 2
#define BB 8
#define SS 256
#define MM (BB*SS)          // 2048
#define RESN 4096
#define HOFF ((size_t)MM * VV)

#define PHI_F 1.6180339887498949f
#define CSC_F 651.8986469044033f          // RES / (2*pi)
#define ANG_F 0.0015339807878856412f      // 2*pi / RES

#define NTT 393                           // ceil(50257/128)
#define VPAD (NTT*128)                    // 50304 padded vocab rows

// ---------------- scratch (static device memory; no allocations) -----------
__device__ float2 g_tab[RESN];
__device__ float  g_X[MM * DD];          // post-MLP: holds tf32-rounded values
__device__ float  g_E[(size_t)MM * 2*DD]; // dense-gathered emb rows (2 MB)
__device__ float  g_Bt[(size_t)VPAD * DD]; // out_w pre-rounded to tf32, zero-padded
__device__ float  g_Wt [LL * DD * NN];   // [l][k][j]  (transposed layer_W)
__device__ float  g_Wrt[LL * NN * DD];   // [l][j][d]  (transposed layer_Wr)
__device__ float  g_Wit[LL * NN * DD];   // [l][j][d]  (transposed layer_Wi)

__device__ __forceinline__ unsigned f2tf32(float v) {
    unsigned u;
    asm("cvt.rna.tf32.f32 %0, %1;" : "=r"(u) : "f"(v));
    return u;
}

// ------- ARM optimized-routines AdvSIMD sinf/cosf (glibc libmvec) ----------
// VALIDATED in R6 (passed). Do not modify.
#define AOR_INVPI  0x1.45f306p-2f
#define AOR_PI1    0x1.921fb6p+1f
#define AOR_PI2   -0x1.777a5cp-24f
#define AOR_PI3   -0x1.ee59dap-49f
#define AOR_SHIFT  0x1.8p+23f
#define AOR_P0    -0x1.555548p-3f
#define AOR_P1     0x1.110df4p-7f
#define AOR_P2    -0x1.9f42eap-13f
#define AOR_P3     0x1.5b2e76p-19f

__device__ __forceinline__ float aor_sin_core(float r, unsigned odd) {
    float r2 = __fmul_rn(r, r);
    float y  = __fmaf_rn(AOR_P3, r2, AOR_P2);
    y = __fmaf_rn(y, r2, AOR_P1);
    y = __fmaf_rn(y, r2, AOR_P0);
    y = __fmaf_rn(__fmul_rn(y, r2), r, r);
    return __uint_as_float(__float_as_uint(y) ^ odd);
}

__device__ __forceinline__ float aor_sinf(float x) {
    float nf = __fmaf_rn(x, AOR_INVPI, AOR_SHIFT);
    unsigned odd = __float_as_uint(nf) << 31;
    float n = __fsub_rn(nf, AOR_SHIFT);
    float r = __fmaf_rn(-AOR_PI1, n, x);
    r = __fmaf_rn(-AOR_PI2, n, r);
    r = __fmaf_rn(-AOR_PI3, n, r);
    return aor_sin_core(r, odd);
}

__device__ __forceinline__ float aor_cosf(float x) {
    float r0 = fabsf(x);
    float nf = __fmaf_rn(r0, AOR_INVPI, 0.5f);
    float t  = __fadd_rn(nf, AOR_SHIFT);
    unsigned odd = __float_as_uint(t) << 31;
    float n = __fsub_rn(__fsub_rn(t, AOR_SHIFT), 0.5f);
    float r = __fmaf_rn(-AOR_PI1, n, r0);
    r = __fmaf_rn(-AOR_PI2, n, r);
    r = __fmaf_rn(-AOR_PI3, n, r);
    return aor_sin_core(r, odd);
}

// ---------------- K0: table + weight transposes + out_w tf32 copy ----------
__global__ void k_init(const float* __restrict__ W,
                       const float* __restrict__ Wr,
                       const float* __restrict__ Wi,
                       const float* __restrict__ OW) {
    int i = blockIdx.x * blockDim.x + threadIdx.x;
    if (i < RESN) {
        float ang = __fmul_rn((float)i, ANG_F);
        g_tab[i] = make_float2(aor_sinf(ang), aor_cosf(ang));
    }
    int o = i - RESN;
    if (o >= 0 && o < LL*NN*DD) {
        int l = o >> 15, k = (o >> 8) & (DD-1), j = o & (NN-1);
        g_Wt[o] = W[l*32768 + j*DD + k];
    }
    int o2 = o - LL*NN*DD;
    if (o2 >= 0 && o2 < LL*NN*DD) {
        int l = o2 >> 15, j = (o2 >> 7) & (NN-1), d = o2 & (DD-1);
        g_Wrt[o2] = Wr[l*32768 + d*NN + j];
    }
    int o3 = o2 - LL*NN*DD;
    if (o3 >= 0 && o3 < LL*NN*DD) {
        int l = o3 >> 15, j = (o3 >> 7) & (NN-1), d = o3 & (DD-1);
        g_Wit[o3] = Wi[l*32768 + d*NN + j];
    }
    // out_w -> g_Bt (tf32 bits), zero-pad rows [VV, VPAD)
    const int NCH = VPAD * (DD/4);              // float4 chunks
    for (int c = i; c < NCH; c += 784*256) {
        int row = c >> 5, k4 = c & 31;
        float4 dv;
        if (row < VV) {
            float4 v = ((const float4*)(OW + (size_t)row*DD))[k4];
            dv.x = __uint_as_float(f2tf32(v.x));
            dv.y = __uint_as_float(f2tf32(v.y));
            dv.z = __uint_as_float(f2tf32(v.z));
            dv.w = __uint_as_float(f2tf32(v.w));
        } else {
            dv.x = dv.y = dv.z = dv.w = 0.f;
        }
        ((float4*)(g_Bt + (size_t)row*DD))[k4] = dv;
    }
}

// ---------------- K0b: dense gather of emb rows ----------------------------
// 2048 blocks x 64 threads: g_E[row] = emb[ids[row]] (one float4/thread).
// Massively parallel -> all DRAM gather latency overlapped here instead of
// serializing inside k_recur's 256-step chain.
__global__ void k_gather(const int* __restrict__ ids,
                         const float* __restrict__ emb) {
    int row = blockIdx.x;
    int id  = ids[row];
    ((float4*)(g_E + (size_t)row*(2*DD)))[threadIdx.x] =
        ((const float4*)(emb + (size_t)id*(2*DD)))[threadIdx.x];
}

// ---------------- K1: elementwise recurrence -> X0, final h ----------------
// Theta arithmetic VALIDATED in R6 — unchanged. Loads now come from the
// dense g_E buffer (bit-identical values) with distance-2 register prefetch
// (~230 cyc budget >= L2 hit 234; g_E is L2-hot from k_gather).
__global__ void k_recur(float* __restrict__ out) {
    __shared__ float2 stab[RESN];
    const int b = blockIdx.x;     // 8 blocks
    const int d = threadIdx.x;    // 128 threads
    for (int i = threadIdx.x; i < RESN; i += 128) stab[i] = g_tab[i];
    __syncthreads();

    const float* eb = g_E + (size_t)(b*SS)*(2*DD);

    float hr = 0.f, hi = 0.f;
    float w0 = eb[d],            b0 = eb[DD + d];            // t = 0
    float w1 = eb[2*DD + d],     b1 = eb[2*DD + DD + d];     // t = 1

    for (int t = 0; t < SS; t++) {
        float wn = 0.f, bn = 0.f;
        if (t + 2 < SS) {
            const float* ep = eb + (size_t)(t + 2)*(2*DD);
            wn = ep[d];
            bn = ep[DD + d];
        }
        float div   = __fdiv_rn(__fadd_rn(hr, hi), __fadd_rn(1.0f, fabsf(w0)));
        float tphi  = __fmul_rn((float)t, PHI_F);
        float theta = __fadd_rn(__fadd_rn(div, b0), tphi);
        int ii = __float2int_rn(__fmul_rn(theta, CSC_F)) & (RESN - 1);
        float2 sc = stab[ii];
        hi = sc.x; hr = sc.y;
        g_X[(b*SS + t)*DD + d] = __fadd_rn(hr, hi);
        w0 = w1; b0 = b1; w1 = wn; b1 = bn;
    }
    out[HOFF + b*DD + d]           = hr;
    out[HOFF + BB*DD + b*DD + d]   = hi;
}

// ---------------- K2: fused 2-layer MLP over 2048 independent rows ---------
// VALIDATED (R9/R13 passed, incl. tf32 pre-rounded write-back). Do not modify.
#define TM 8
__global__ __launch_bounds__(256) void k_mlp(const float* __restrict__ bvec) {
    __shared__ __align__(16) float xs[TM][DD];
    __shared__ __align__(16) float cs[TM][NN];
    __shared__ __align__(16) float sn[TM][NN];
    const int tid = threadIdx.x;
    const int r0  = blockIdx.x * TM;

    for (int i = tid; i < TM*DD; i += 256)
        xs[i >> 7][i & (DD-1)] = g_X[(r0 + (i >> 7))*DD + (i & (DD-1))];

    for (int l = 0; l < LL; l++) {
        __syncthreads();
        float acc[TM];
        #pragma unroll
        for (int r = 0; r < TM; r++) acc[r] = 0.f;
        const float* wt = g_Wt + l*DD*NN;
        #pragma unroll 2
        for (int k4 = 0; k4 < DD/4; k4++) {
            float4 xv[TM];
            #pragma unroll
            for (int r = 0; r < TM; r++)
                xv[r] = ((const float4*)xs[r])[k4];
            #pragma unroll
            for (int kk = 0; kk < 4; kk++) {
                float wv = wt[(k4*4 + kk)*NN + tid];
                #pragma unroll
                for (int r = 0; r < TM; r++) {
                    float x = (kk == 0) ? xv[r].x : (kk == 1) ? xv[r].y :
                              (kk == 2) ? xv[r].z : xv[r].w;
                    acc[r] += x * wv;
                }
            }
        }
        float bj = bvec[l*NN + tid];
        #pragma unroll
        for (int r = 0; r < TM; r++) {
            float tphi = (float)((r0 + r) & (SS-1)) * PHI_F;
            float th = (acc[r] + bj) + tphi;
            int ii = __float2int_rn(th * CSC_F) & (RESN - 1);
            float2 sc = g_tab[ii];
            sn[r][tid] = sc.x;
            cs[r][tid] = sc.y;
        }
        __syncthreads();
        const int dg = tid & 31;
        const int r  = tid >> 5;
        const float4* wr4 = (const float4*)(g_Wrt + l*NN*DD);
        const float4* wi4 = (const float4*)(g_Wit + l*NN*DD);
        float o0 = 0.f, o1 = 0.f, o2 = 0.f, o3 = 0.f;
        #pragma unroll 2
        for (int j4 = 0; j4 < NN/4; j4++) {
            float4 cv = ((const float4*)cs[r])[j4];
            float4 sv = ((const float4*)sn[r])[j4];
            #pragma unroll
            for (int jj = 0; jj < 4; jj++) {
                int j = j4*4 + jj;
                float4 a  = wr4[j*(DD/4) + dg];
                float4 b2 = wi4[j*(DD/4) + dg];
                float c = (jj == 0) ? cv.x : (jj == 1) ? cv.y : (jj == 2) ? cv.z : cv.w;
                float s = (jj == 0) ? sv.x : (jj == 1) ? sv.y : (jj == 2) ? sv.z : sv.w;
                o0 += c*a.x + s*b2.x;
                o1 += c*a.y + s*b2.y;
                o2 += c*a.z + s*b2.z;
                o3 += c*a.w + s*b2.w;
            }
        }
        int dbase = dg * 4;
        float ov[4] = {o0, o1, o2, o3};
        #pragma unroll
        for (int q = 0; q < 4; q++) {
            float o = ov[q];
            float sg = 1.0f / (1.0f + expf(-o));
            xs[r][dbase + q] += o * sg;
        }
    }
    __syncthreads();
    // write-back pre-rounded to tf32 (bit pattern is a valid f32)
    for (int i = tid; i < TM*DD; i += 256)
        g_X[(r0 + (i >> 7))*DD + (i & (DD-1))] =
            __uint_as_float(f2tf32(xs[i >> 7][i & (DD-1)]));
}

// ---------------- K3: logits GEMM (M=2048, N=50257, K=128), tf32 mma.sync --
// v6 VALIDATED R13 (219.5us). Do not modify.
#define PA 132
#define K3_SMEM ((64*PA + 128*PA)*4)     // 101376 B -> 2 CTAs/SM
#define K3_GRID 296
#define K3_ITEMS (NTT*32)                // 12576 (393 nt x 32 m-chunks of 64)

__device__ __forceinline__ void ldsm_x4(unsigned& r0, unsigned& r1,
                                        unsigned& r2, unsigned& r3, unsigned addr) {
    asm volatile("ldmatrix.sync.aligned.m8n8.x4.shared.b16 {%0,%1,%2,%3}, [%4];"
                 : "=r"(r0), "=r"(r1), "=r"(r2), "=r"(r3) : "r"(addr));
}
__device__ __forceinline__ void cpa16(unsigned dst, const float* src) {
    asm volatile("cp.async.cg.shared.global [%0], [%1], 16;"
                 :: "r"(dst), "l"(src));
}

__global__ __launch_bounds__(256, 2) void k_gemm(const float* __restrict__ Bmat,
                                                 float* __restrict__ out) {
    extern __shared__ unsigned smemu[];
    float* Os = (float*)smemu;               // 64 x 129 floats, aliases As region

    const int tid  = threadIdx.x;
    const int warp = tid >> 5, lane = tid & 31;
    const int grp  = lane >> 2, tig = lane & 3;
    const int wm   = (warp >> 2) * 32;       // warp row base (0 or 32)
    const int wn   = (warp & 3) * 32;        // warp col base (0,32,64,96)

    const unsigned sbase  = (unsigned)__cvta_generic_to_shared(smemu);
    const unsigned bs_u32 = sbase + 64u*PA*4u;

    // validated ldmatrix lane addressing (R8/R9)
    const unsigned aBase = sbase + (unsigned)((wm + (lane & 15))*PA)*4u
                                 + (unsigned)(lane >> 4)*16u;
    const unsigned bBase = bs_u32 + (unsigned)((wn + ((lane >> 4) & 1)*8 + (lane & 7))*PA)*4u
                                  + (unsigned)((lane >> 3) & 1)*16u;

    const int start = (int)(((long long)blockIdx.x       * K3_ITEMS) / K3_GRID);
    const int stop  = (int)(((long long)(blockIdx.x + 1) * K3_ITEMS) / K3_GRID);
    if (start >= stop) return;

    // prologue: async copy A of first item (pure copy: g_X already tf32)
    {
        const float* src = g_X + (size_t)((start & 31) * 64) * DD;
        #pragma unroll
        for (int it = 0; it < 8; it++) {
            int c = tid + it*256;                // 2048 16B chunks (64 rows)
            int r = c >> 5, k4 = c & 31;
            cpa16(sbase + (unsigned)(r*PA + k4*4)*4u, src + r*DD + k4*4);
        }
        asm volatile("cp.async.commit_group;" ::: "memory");
    }

    int cur_nt = -1;
    for (int item = start; item < stop; item++) {
        const int nt = item >> 5, mc = item & 31;
        const int n0 = nt * 128, m0 = mc * 64;

        asm volatile("cp.async.wait_group 0;" ::: "memory");
        __syncthreads();      // A visible to all

        if (nt != cur_nt) {   // stage B: pure async copy from padded g_Bt
            #pragma unroll
            for (int it = 0; it < 16; it++) {
                int c = tid + it*256;            // 4096 chunks (128 rows)
                int r = c >> 5, k4 = c & 31;
                cpa16(bs_u32 + (unsigned)(r*PA + k4*4)*4u,
                      g_Bt + (size_t)(n0 + r)*DD + k4*4);
            }
            asm volatile("cp.async.commit_group;" ::: "memory");
            asm volatile("cp.async.wait_group 0;" ::: "memory");
            cur_nt = nt;
            __syncthreads();
        }

        // ---- compute: 16 k-steps, warp tile 32x32 ----
        float acc[2][4][4];
        #pragma unroll
        for (int mi = 0; mi < 2; mi++)
            #pragma unroll
            for (int ni = 0; ni < 4; ni++)
                #pragma unroll
                for (int q = 0; q < 4; q++) acc[mi][ni][q] = 0.f;

        #pragma unroll
        for (int kk = 0; kk < 16; kk++) {
            const unsigned koff = kk * 32u;
            unsigned a[2][4], b[2][4];
            ldsm_x4(a[0][0], a[0][1], a[0][2], a[0][3], aBase + koff);
            ldsm_x4(a[1][0], a[1][1], a[1][2], a[1][3], aBase + 16u*PA*4u + koff);
            ldsm_x4(b[0][0], b[0][1], b[0][2], b[0][3], bBase + koff);
            ldsm_x4(b[1][0], b[1][1], b[1][2], b[1][3], bBase + 16u*PA*4u + koff);
            #pragma unroll
            for (int ni = 0; ni < 4; ni++) {
                unsigned b0 = b[ni >> 1][(ni & 1)*2];
                unsigned b1 = b[ni >> 1][(ni & 1)*2 + 1];
                #pragma unroll
                for (int mi = 0; mi < 2; mi++) {
                    asm volatile(
                        "mma.sync.aligned.m16n8k8.row.col.f32.tf32.tf32.f32 "
                        "{%0,%1,%2,%3}, {%4,%5,%6,%7}, {%8,%9}, {%0,%1,%2,%3};"
                        : "+f"(acc[mi][ni][0]), "+f"(acc[mi][ni][1]),
                          "+f"(acc[mi][ni][2]), "+f"(acc[mi][ni][3])
                        : "r"(a[mi][0]), "r"(a[mi][1]), "r"(a[mi][2]), "r"(a[mi][3]),
                          "r"(b0), "r"(b1));
                }
            }
        }
        __syncthreads();      // all LDSM reads of As done (Os aliases As)

        // ---- staged epilogue: acc -> Os (smem) ----
        #pragma unroll
        for (int mi = 0; mi < 2; mi++) {
            #pragma unroll
            for (int ni = 0; ni < 4; ni++) {
                int rr = wm + mi*16 + grp;
                int cc = wn + ni*8 + 2*tig;
                Os[rr*129 + cc]       = acc[mi][ni][0];
                Os[rr*129 + cc + 1]   = acc[mi][ni][1];
                Os[(rr+8)*129 + cc]   = acc[mi][ni][2];
                Os[(rr+8)*129 + cc+1] = acc[mi][ni][3];
            }
        }
        __syncthreads();

        // ---- row-coalesced global stores ----
        #pragma unroll 4
        for (int i = tid; i < 64*128; i += 256) {
            int r = i >> 7, c = i & 127;
            int col = n0 + c;
            if (col < VV)
                out[(size_t)(m0 + r)*VV + col] = Os[r*129 + c];
        }
        __syncthreads();      // Os reads done before next A overwrites region

        if (item + 1 < stop) {   // async copy next A
            const float* src = g_X + (size_t)(((item + 1) & 31) * 64) * DD;
            #pragma unroll
            for (int it = 0; it < 8; it++) {
                int c = tid + it*256;
                int r = c >> 5, k4 = c & 31;
                cpa16(sbase + (unsigned)(r*PA + k4*4)*4u, src + r*DD + k4*4);
            }
            asm volatile("cp.async.commit_group;" ::: "memory");
        }
    }
}

// ---------------- launch ---------------------------------------------------
extern "C" void kernel_launch(void* const* d_in, const int* in_sizes, int n_in,
                              void* d_out, int out_size) {
    const int*   ids = (const int*)  d_in[0];
    const float* emb = (const float*)d_in[1];
    const float* W   = (const float*)d_in[2];
    const float* bv  = (const float*)d_in[3];
    const float* Wr  = (const float*)d_in[4];
    const float* Wi  = (const float*)d_in[5];
    const float* ow  = (const float*)d_in[6];
    float* out = (float*)d_out;

    (void)cudaFuncSetAttribute(k_gemm, cudaFuncAttributeMaxDynamicSharedMemorySize, K3_SMEM);

    k_init  <<<784, 256>>>(W, Wr, Wi, ow);
    k_gather<<<MM, 64>>>(ids, emb);
    k_recur <<<BB, 128>>>(out);
    k_mlp   <<<MM/TM, 256>>>(bv);
    k_gemm  <<<K3_GRID, 256, K3_SMEM>>>(ow, out);
}

// round 15
// speedup vs baseline: 1.5422x; 1.0294x over previous
#include <cuda_runtime.h>
#include <math.h>
#include <stdint.h>

#define VV 50257
#define DD 128
#define NN 256
#define LL 2
#define BB 8
#define SS 256
#define MM (BB*SS)          // 2048
#define RESN 4096
#define HOFF ((size_t)MM * VV)

#define PHI_F 1.6180339887498949f
#define CSC_F 651.8986469044033f          // RES / (2*pi)
#define ANG_F 0.0015339807878856412f      // 2*pi / RES

#define NTT 393                           // ceil(50257/128)
#define VPAD (NTT*128)                    // 50304 padded vocab rows

// ---------------- scratch (static device memory; no allocations) -----------
__device__ float2 g_tab[RESN];
__device__ float  g_X[MM * DD];          // post-MLP: holds tf32-rounded values
__device__ float  g_E[(size_t)MM * 2*DD]; // dense-gathered emb rows (2 MB)
__device__ float  g_Bt[(size_t)VPAD * DD]; // out_w pre-rounded to tf32, zero-padded
__device__ float  g_Wt [LL * DD * NN];   // [l][k][j]  (transposed layer_W)
__device__ float  g_Wrt[LL * NN * DD];   // [l][j][d]  (transposed layer_Wr)
__device__ float  g_Wit[LL * NN * DD];   // [l][j][d]  (transposed layer_Wi)

__device__ __forceinline__ unsigned f2tf32(float v) {
    unsigned u;
    asm("cvt.rna.tf32.f32 %0, %1;" : "=r"(u) : "f"(v));
    return u;
}

// ------- ARM optimized-routines AdvSIMD sinf/cosf (glibc libmvec) ----------
// VALIDATED in R6 (passed). Do not modify.
#define AOR_INVPI  0x1.45f306p-2f
#define AOR_PI1    0x1.921fb6p+1f
#define AOR_PI2   -0x1.777a5cp-24f
#define AOR_PI3   -0x1.ee59dap-49f
#define AOR_SHIFT  0x1.8p+23f
#define AOR_P0    -0x1.555548p-3f
#define AOR_P1     0x1.110df4p-7f
#define AOR_P2    -0x1.9f42eap-13f
#define AOR_P3     0x1.5b2e76p-19f

__device__ __forceinline__ float aor_sin_core(float r, unsigned odd) {
    float r2 = __fmul_rn(r, r);
    float y  = __fmaf_rn(AOR_P3, r2, AOR_P2);
    y = __fmaf_rn(y, r2, AOR_P1);
    y = __fmaf_rn(y, r2, AOR_P0);
    y = __fmaf_rn(__fmul_rn(y, r2), r, r);
    return __uint_as_float(__float_as_uint(y) ^ odd);
}

__device__ __forceinline__ float aor_sinf(float x) {
    float nf = __fmaf_rn(x, AOR_INVPI, AOR_SHIFT);
    unsigned odd = __float_as_uint(nf) << 31;
    float n = __fsub_rn(nf, AOR_SHIFT);
    float r = __fmaf_rn(-AOR_PI1, n, x);
    r = __fmaf_rn(-AOR_PI2, n, r);
    r = __fmaf_rn(-AOR_PI3, n, r);
    return aor_sin_core(r, odd);
}

__device__ __forceinline__ float aor_cosf(float x) {
    float r0 = fabsf(x);
    float nf = __fmaf_rn(r0, AOR_INVPI, 0.5f);
    float t  = __fadd_rn(nf, AOR_SHIFT);
    unsigned odd = __float_as_uint(t) << 31;
    float n = __fsub_rn(__fsub_rn(t, AOR_SHIFT), 0.5f);
    float r = __fmaf_rn(-AOR_PI1, n, r0);
    r = __fmaf_rn(-AOR_PI2, n, r);
    r = __fmaf_rn(-AOR_PI3, n, r);
    return aor_sin_core(r, odd);
}

// ---------------- K0: table + weight transposes + out_w tf32 copy ----------
__global__ void k_init(const float* __restrict__ W,
                       const float* __restrict__ Wr,
                       const float* __restrict__ Wi,
                       const float* __restrict__ OW) {
    int i = blockIdx.x * blockDim.x + threadIdx.x;
    if (i < RESN) {
        float ang = __fmul_rn((float)i, ANG_F);
        g_tab[i] = make_float2(aor_sinf(ang), aor_cosf(ang));
    }
    int o = i - RESN;
    if (o >= 0 && o < LL*NN*DD) {
        int l = o >> 15, k = (o >> 8) & (DD-1), j = o & (NN-1);
        g_Wt[o] = W[l*32768 + j*DD + k];
    }
    int o2 = o - LL*NN*DD;
    if (o2 >= 0 && o2 < LL*NN*DD) {
        int l = o2 >> 15, j = (o2 >> 7) & (NN-1), d = o2 & (DD-1);
        g_Wrt[o2] = Wr[l*32768 + d*NN + j];
    }
    int o3 = o2 - LL*NN*DD;
    if (o3 >= 0 && o3 < LL*NN*DD) {
        int l = o3 >> 15, j = (o3 >> 7) & (NN-1), d = o3 & (DD-1);
        g_Wit[o3] = Wi[l*32768 + d*NN + j];
    }
    // out_w -> g_Bt (tf32 bits), zero-pad rows [VV, VPAD)
    const int NCH = VPAD * (DD/4);              // float4 chunks
    for (int c = i; c < NCH; c += 784*256) {
        int row = c >> 5, k4 = c & 31;
        float4 dv;
        if (row < VV) {
            float4 v = ((const float4*)(OW + (size_t)row*DD))[k4];
            dv.x = __uint_as_float(f2tf32(v.x));
            dv.y = __uint_as_float(f2tf32(v.y));
            dv.z = __uint_as_float(f2tf32(v.z));
            dv.w = __uint_as_float(f2tf32(v.w));
        } else {
            dv.x = dv.y = dv.z = dv.w = 0.f;
        }
        ((float4*)(g_Bt + (size_t)row*DD))[k4] = dv;
    }
}

// ---------------- K0b: dense gather of emb rows (VALIDATED R14) ------------
__global__ void k_gather(const int* __restrict__ ids,
                         const float* __restrict__ emb) {
    int row = blockIdx.x;
    int id  = ids[row];
    ((float4*)(g_E + (size_t)row*(2*DD)))[threadIdx.x] =
        ((const float4*)(emb + (size_t)id*(2*DD)))[threadIdx.x];
}

// ---------------- K1: elementwise recurrence (VALIDATED R14) ---------------
__global__ void k_recur(float* __restrict__ out) {
    __shared__ float2 stab[RESN];
    const int b = blockIdx.x;     // 8 blocks
    const int d = threadIdx.x;    // 128 threads
    for (int i = threadIdx.x; i < RESN; i += 128) stab[i] = g_tab[i];
    __syncthreads();

    const float* eb = g_E + (size_t)(b*SS)*(2*DD);

    float hr = 0.f, hi = 0.f;
    float w0 = eb[d],            b0 = eb[DD + d];            // t = 0
    float w1 = eb[2*DD + d],     b1 = eb[2*DD + DD + d];     // t = 1

    for (int t = 0; t < SS; t++) {
        float wn = 0.f, bn = 0.f;
        if (t + 2 < SS) {
            const float* ep = eb + (size_t)(t + 2)*(2*DD);
            wn = ep[d];
            bn = ep[DD + d];
        }
        float div   = __fdiv_rn(__fadd_rn(hr, hi), __fadd_rn(1.0f, fabsf(w0)));
        float tphi  = __fmul_rn((float)t, PHI_F);
        float theta = __fadd_rn(__fadd_rn(div, b0), tphi);
        int ii = __float2int_rn(__fmul_rn(theta, CSC_F)) & (RESN - 1);
        float2 sc = stab[ii];
        hi = sc.x; hr = sc.y;
        g_X[(b*SS + t)*DD + d] = __fadd_rn(hr, hi);
        w0 = w1; b0 = b1; w1 = wn; b1 = bn;
    }
    out[HOFF + b*DD + d]           = hr;
    out[HOFF + BB*DD + b*DD + d]   = hi;
}

// ---------------- K2: fused 2-layer MLP, v2 --------------------------------
// Same math / same per-element accumulation order as the R13-validated
// version. Changes: TM 8->4 (grid 512 -> occ 43%), phase-2 remapped to
// 2 d per thread (float2 weight loads) with 4-j batched inner loop (MLP~10),
// phase-1 k-loop unroll 4.
#define TM 4
__global__ __launch_bounds__(256) void k_mlp(const float* __restrict__ bvec) {
    __shared__ __align__(16) float xs[TM][DD];
    __shared__ __align__(16) float cs[TM][NN];
    __shared__ __align__(16) float sn[TM][NN];
    const int tid = threadIdx.x;
    const int r0  = blockIdx.x * TM;

    for (int i = tid; i < TM*DD; i += 256)
        xs[i >> 7][i & (DD-1)] = g_X[(r0 + (i >> 7))*DD + (i & (DD-1))];

    for (int l = 0; l < LL; l++) {
        __syncthreads();
        // ---- phase 1: th[r][j] for j = tid, all TM rows (k ascending) ----
        float acc[TM];
        #pragma unroll
        for (int r = 0; r < TM; r++) acc[r] = 0.f;
        const float* wt = g_Wt + l*DD*NN;
        #pragma unroll 4
        for (int k4 = 0; k4 < DD/4; k4++) {
            float4 xv[TM];
            #pragma unroll
            for (int r = 0; r < TM; r++)
                xv[r] = ((const float4*)xs[r])[k4];
            float wv0 = wt[(k4*4 + 0)*NN + tid];
            float wv1 = wt[(k4*4 + 1)*NN + tid];
            float wv2 = wt[(k4*4 + 2)*NN + tid];
            float wv3 = wt[(k4*4 + 3)*NN + tid];
            #pragma unroll
            for (int r = 0; r < TM; r++) {
                acc[r] += xv[r].x * wv0;
                acc[r] += xv[r].y * wv1;
                acc[r] += xv[r].z * wv2;
                acc[r] += xv[r].w * wv3;
            }
        }
        float bj = bvec[l*NN + tid];
        #pragma unroll
        for (int r = 0; r < TM; r++) {
            float tphi = (float)((r0 + r) & (SS-1)) * PHI_F;
            float th = (acc[r] + bj) + tphi;
            int ii = __float2int_rn(th * CSC_F) & (RESN - 1);
            float2 sc = g_tab[ii];
            sn[r][tid] = sc.x;
            cs[r][tid] = sc.y;
        }
        __syncthreads();
        // ---- phase 2: o[r][d], 2 d per thread, j ascending ----
        const int dg = tid & 63;          // 64 d-pairs -> d = 2*dg, 2*dg+1
        const int r  = tid >> 6;          // 4 rows
        const float2* wr2 = (const float2*)(g_Wrt + l*NN*DD);
        const float2* wi2 = (const float2*)(g_Wit + l*NN*DD);
        float o0 = 0.f, o1 = 0.f;
        #pragma unroll 2
        for (int j4 = 0; j4 < NN/4; j4++) {
            float4 cv = ((const float4*)cs[r])[j4];
            float4 sv = ((const float4*)sn[r])[j4];
            int jb = j4*4;
            float2 a0 = wr2[(jb+0)*64 + dg];
            float2 a1 = wr2[(jb+1)*64 + dg];
            float2 a2 = wr2[(jb+2)*64 + dg];
            float2 a3 = wr2[(jb+3)*64 + dg];
            float2 b0 = wi2[(jb+0)*64 + dg];
            float2 b1 = wi2[(jb+1)*64 + dg];
            float2 b2 = wi2[(jb+2)*64 + dg];
            float2 b3 = wi2[(jb+3)*64 + dg];
            o0 += cv.x*a0.x + sv.x*b0.x;
            o1 += cv.x*a0.y + sv.x*b0.y;
            o0 += cv.y*a1.x + sv.y*b1.x;
            o1 += cv.y*a1.y + sv.y*b1.y;
            o0 += cv.z*a2.x + sv.z*b2.x;
            o1 += cv.z*a2.y + sv.z*b2.y;
            o0 += cv.w*a3.x + sv.w*b3.x;
            o1 += cv.w*a3.y + sv.w*b3.y;
        }
        {
            float sg0 = 1.0f / (1.0f + expf(-o0));
            float sg1 = 1.0f / (1.0f + expf(-o1));
            xs[r][2*dg]     += o0 * sg0;
            xs[r][2*dg + 1] += o1 * sg1;
        }
    }
    __syncthreads();
    // write-back pre-rounded to tf32 (bit pattern is a valid f32)
    for (int i = tid; i < TM*DD; i += 256)
        g_X[(r0 + (i >> 7))*DD + (i & (DD-1))] =
            __uint_as_float(f2tf32(xs[i >> 7][i & (DD-1)]));
}

// ---------------- K3: logits GEMM (VALIDATED R13, 219.5us). Frozen. --------
#define PA 132
#define K3_SMEM ((64*PA + 128*PA)*4)     // 101376 B -> 2 CTAs/SM
#define K3_GRID 296
#define K3_ITEMS (NTT*32)                // 12576 (393 nt x 32 m-chunks of 64)

__device__ __forceinline__ void ldsm_x4(unsigned& r0, unsigned& r1,
                                        unsigned& r2, unsigned& r3, unsigned addr) {
    asm volatile("ldmatrix.sync.aligned.m8n8.x4.shared.b16 {%0,%1,%2,%3}, [%4];"
                 : "=r"(r0), "=r"(r1), "=r"(r2), "=r"(r3) : "r"(addr));
}
__device__ __forceinline__ void cpa16(unsigned dst, const float* src) {
    asm volatile("cp.async.cg.shared.global [%0], [%1], 16;"
                 :: "r"(dst), "l"(src));
}

__global__ __launch_bounds__(256, 2) void k_gemm(const float* __restrict__ Bmat,
                                                 float* __restrict__ out) {
    extern __shared__ unsigned smemu[];
    float* Os = (float*)smemu;               // 64 x 129 floats, aliases As region

    const int tid  = threadIdx.x;
    const int warp = tid >> 5, lane = tid & 31;
    const int grp  = lane >> 2, tig = lane & 3;
    const int wm   = (warp >> 2) * 32;       // warp row base (0 or 32)
    const int wn   = (warp & 3) * 32;        // warp col base (0,32,64,96)

    const unsigned sbase  = (unsigned)__cvta_generic_to_shared(smemu);
    const unsigned bs_u32 = sbase + 64u*PA*4u;

    const unsigned aBase = sbase + (unsigned)((wm + (lane & 15))*PA)*4u
                                 + (unsigned)(lane >> 4)*16u;
    const unsigned bBase = bs_u32 + (unsigned)((wn + ((lane >> 4) & 1)*8 + (lane & 7))*PA)*4u
                                  + (unsigned)((lane >> 3) & 1)*16u;

    const int start = (int)(((long long)blockIdx.x       * K3_ITEMS) / K3_GRID);
    const int stop  = (int)(((long long)(blockIdx.x + 1) * K3_ITEMS) / K3_GRID);
    if (start >= stop) return;

    {
        const float* src = g_X + (size_t)((start & 31) * 64) * DD;
        #pragma unroll
        for (int it = 0; it < 8; it++) {
            int c = tid + it*256;                // 2048 16B chunks (64 rows)
            int r = c >> 5, k4 = c & 31;
            cpa16(sbase + (unsigned)(r*PA + k4*4)*4u, src + r*DD + k4*4);
        }
        asm volatile("cp.async.commit_group;" ::: "memory");
    }

    int cur_nt = -1;
    for (int item = start; item < stop; item++) {
        const int nt = item >> 5, mc = item & 31;
        const int n0 = nt * 128, m0 = mc * 64;

        asm volatile("cp.async.wait_group 0;" ::: "memory");
        __syncthreads();      // A visible to all

        if (nt != cur_nt) {   // stage B: pure async copy from padded g_Bt
            #pragma unroll
            for (int it = 0; it < 16; it++) {
                int c = tid + it*256;            // 4096 chunks (128 rows)
                int r = c >> 5, k4 = c & 31;
                cpa16(bs_u32 + (unsigned)(r*PA + k4*4)*4u,
                      g_Bt + (size_t)(n0 + r)*DD + k4*4);
            }
            asm volatile("cp.async.commit_group;" ::: "memory");
            asm volatile("cp.async.wait_group 0;" ::: "memory");
            cur_nt = nt;
            __syncthreads();
        }

        float acc[2][4][4];
        #pragma unroll
        for (int mi = 0; mi < 2; mi++)
            #pragma unroll
            for (int ni = 0; ni < 4; ni++)
                #pragma unroll
                for (int q = 0; q < 4; q++) acc[mi][ni][q] = 0.f;

        #pragma unroll
        for (int kk = 0; kk < 16; kk++) {
            const unsigned koff = kk * 32u;
            unsigned a[2][4], b[2][4];
            ldsm_x4(a[0][0], a[0][1], a[0][2], a[0][3], aBase + koff);
            ldsm_x4(a[1][0], a[1][1], a[1][2], a[1][3], aBase + 16u*PA*4u + koff);
            ldsm_x4(b[0][0], b[0][1], b[0][2], b[0][3], bBase + koff);
            ldsm_x4(b[1][0], b[1][1], b[1][2], b[1][3], bBase + 16u*PA*4u + koff);
            #pragma unroll
            for (int ni = 0; ni < 4; ni++) {
                unsigned b0 = b[ni >> 1][(ni & 1)*2];
                unsigned b1 = b[ni >> 1][(ni & 1)*2 + 1];
                #pragma unroll
                for (int mi = 0; mi < 2; mi++) {
                    asm volatile(
                        "mma.sync.aligned.m16n8k8.row.col.f32.tf32.tf32.f32 "
                        "{%0,%1,%2,%3}, {%4,%5,%6,%7}, {%8,%9}, {%0,%1,%2,%3};"
                        : "+f"(acc[mi][ni][0]), "+f"(acc[mi][ni][1]),
                          "+f"(acc[mi][ni][2]), "+f"(acc[mi][ni][3])
                        : "r"(a[mi][0]), "r"(a[mi][1]), "r"(a[mi][2]), "r"(a[mi][3]),
                          "r"(b0), "r"(b1));
                }
            }
        }
        __syncthreads();      // all LDSM reads of As done (Os aliases As)

        #pragma unroll
        for (int mi = 0; mi < 2; mi++) {
            #pragma unroll
            for (int ni = 0; ni < 4; ni++) {
                int rr = wm + mi*16 + grp;
                int cc = wn + ni*8 + 2*tig;
                Os[rr*129 + cc]       = acc[mi][ni][0];
                Os[rr*129 + cc + 1]   = acc[mi][ni][1];
                Os[(rr+8)*129 + cc]   = acc[mi][ni][2];
                Os[(rr+8)*129 + cc+1] = acc[mi][ni][3];
            }
        }
        __syncthreads();

        #pragma unroll 4
        for (int i = tid; i < 64*128; i += 256) {
            int r = i >> 7, c = i & 127;
            int col = n0 + c;
            if (col < VV)
                out[(size_t)(m0 + r)*VV + col] = Os[r*129 + c];
        }
        __syncthreads();      // Os reads done before next A overwrites region

        if (item + 1 < stop) {
            const float* src = g_X + (size_t)(((item + 1) & 31) * 64) * DD;
            #pragma unroll
            for (int it = 0; it < 8; it++) {
                int c = tid + it*256;
                int r = c >> 5, k4 = c & 31;
                cpa16(sbase + (unsigned)(r*PA + k4*4)*4u, src + r*DD + k4*4);
            }
            asm volatile("cp.async.commit_group;" ::: "memory");
        }
    }
}

// ---------------- launch ---------------------------------------------------
extern "C" void kernel_launch(void* const* d_in, const int* in_sizes, int n_in,
                              void* d_out, int out_size) {
    const int*   ids = (const int*)  d_in[0];
    const float* emb = (const float*)d_in[1];
    const float* W   = (const float*)d_in[2];
    const float* bv  = (const float*)d_in[3];
    const float* Wr  = (const float*)d_in[4];
    const float* Wi  = (const float*)d_in[5];
    const float* ow  = (const float*)d_in[6];
    float* out = (float*)d_out;

    (void)cudaFuncSetAttribute(k_gemm, cudaFuncAttributeMaxDynamicSharedMemorySize, K3_SMEM);

    k_init  <<<784, 256>>>(W, Wr, Wi, ow);
    k_gather<<<MM, 64>>>(ids, emb);
    k_recur <<<BB, 128>>>(out);
    k_mlp   <<<MM/TM, 256>>>(bv);
    k_gemm  <<<K3_GRID, 256, K3_SMEM>>>(ow, out);
}

// round 16
// speedup vs baseline: 1.8216x; 1.1812x over previous
#include <cuda_runtime.h>
#include <math.h>
#include <stdint.h>

#define VV 50257
#define DD 128
#define NN 256
#define LL 2
#define BB 8
#define SS 256
#define MM (BB*SS)          // 2048
#define RESN 4096
#define HOFF ((size_t)MM * VV)

#define PHI_F 1.6180339887498949f
#define CSC_F 651.8986469044033f          // RES / (2*pi)
#define ANG_F 0.0015339807878856412f      // 2*pi / RES

#define NTT 393                           // ceil(50257/128)
#define VPAD (NTT*128)                    // 50304 padded vocab rows

// ---------------- scratch (static device memory; no allocations) -----------
__device__ float2 g_tab[RESN];
__device__ float  g_X[MM * DD];          // post-MLP: holds tf32-rounded values
__device__ float  g_E[(size_t)MM * 2*DD]; // dense-gathered emb rows (2 MB)
__device__ float  g_Bt[(size_t)VPAD * DD]; // out_w pre-rounded to tf32, zero-padded
__device__ float  g_Wt [LL * DD * NN];   // [l][k][j]  (transposed layer_W)
__device__ float  g_Wrt[LL * NN * DD];   // [l][j][d]  (transposed layer_Wr)
__device__ float  g_Wit[LL * NN * DD];   // [l][j][d]  (transposed layer_Wi)

__device__ __forceinline__ unsigned f2tf32(float v) {
    unsigned u;
    asm("cvt.rna.tf32.f32 %0, %1;" : "=r"(u) : "f"(v));
    return u;
}
__device__ __forceinline__ void cpa16(unsigned dst, const float* src) {
    asm volatile("cp.async.cg.shared.global [%0], [%1], 16;"
                 :: "r"(dst), "l"(src));
}

// ------- ARM optimized-routines AdvSIMD sinf/cosf (glibc libmvec) ----------
// VALIDATED in R6 (passed). Do not modify.
#define AOR_INVPI  0x1.45f306p-2f
#define AOR_PI1    0x1.921fb6p+1f
#define AOR_PI2   -0x1.777a5cp-24f
#define AOR_PI3   -0x1.ee59dap-49f
#define AOR_SHIFT  0x1.8p+23f
#define AOR_P0    -0x1.555548p-3f
#define AOR_P1     0x1.110df4p-7f
#define AOR_P2    -0x1.9f42eap-13f
#define AOR_P3     0x1.5b2e76p-19f

__device__ __forceinline__ float aor_sin_core(float r, unsigned odd) {
    float r2 = __fmul_rn(r, r);
    float y  = __fmaf_rn(AOR_P3, r2, AOR_P2);
    y = __fmaf_rn(y, r2, AOR_P1);
    y = __fmaf_rn(y, r2, AOR_P0);
    y = __fmaf_rn(__fmul_rn(y, r2), r, r);
    return __uint_as_float(__float_as_uint(y) ^ odd);
}

__device__ __forceinline__ float aor_sinf(float x) {
    float nf = __fmaf_rn(x, AOR_INVPI, AOR_SHIFT);
    unsigned odd = __float_as_uint(nf) << 31;
    float n = __fsub_rn(nf, AOR_SHIFT);
    float r = __fmaf_rn(-AOR_PI1, n, x);
    r = __fmaf_rn(-AOR_PI2, n, r);
    r = __fmaf_rn(-AOR_PI3, n, r);
    return aor_sin_core(r, odd);
}

__device__ __forceinline__ float aor_cosf(float x) {
    float r0 = fabsf(x);
    float nf = __fmaf_rn(r0, AOR_INVPI, 0.5f);
    float t  = __fadd_rn(nf, AOR_SHIFT);
    unsigned odd = __float_as_uint(t) << 31;
    float n = __fsub_rn(__fsub_rn(t, AOR_SHIFT), 0.5f);
    float r = __fmaf_rn(-AOR_PI1, n, r0);
    r = __fmaf_rn(-AOR_PI2, n, r);
    r = __fmaf_rn(-AOR_PI3, n, r);
    return aor_sin_core(r, odd);
}

// ---------------- K0: table + weight transposes + out_w tf32 copy ----------
__global__ void k_init(const float* __restrict__ W,
                       const float* __restrict__ Wr,
                       const float* __restrict__ Wi,
                       const float* __restrict__ OW) {
    int i = blockIdx.x * blockDim.x + threadIdx.x;
    if (i < RESN) {
        float ang = __fmul_rn((float)i, ANG_F);
        g_tab[i] = make_float2(aor_sinf(ang), aor_cosf(ang));
    }
    int o = i - RESN;
    if (o >= 0 && o < LL*NN*DD) {
        int l = o >> 15, k = (o >> 8) & (DD-1), j = o & (NN-1);
        g_Wt[o] = W[l*32768 + j*DD + k];
    }
    int o2 = o - LL*NN*DD;
    if (o2 >= 0 && o2 < LL*NN*DD) {
        int l = o2 >> 15, j = (o2 >> 7) & (NN-1), d = o2 & (DD-1);
        g_Wrt[o2] = Wr[l*32768 + d*NN + j];
    }
    int o3 = o2 - LL*NN*DD;
    if (o3 >= 0 && o3 < LL*NN*DD) {
        int l = o3 >> 15, j = (o3 >> 7) & (NN-1), d = o3 & (DD-1);
        g_Wit[o3] = Wi[l*32768 + d*NN + j];
    }
    // out_w -> g_Bt (tf32 bits), zero-pad rows [VV, VPAD)
    const int NCH = VPAD * (DD/4);              // float4 chunks
    for (int c = i; c < NCH; c += 784*256) {
        int row = c >> 5, k4 = c & 31;
        float4 dv;
        if (row < VV) {
            float4 v = ((const float4*)(OW + (size_t)row*DD))[k4];
            dv.x = __uint_as_float(f2tf32(v.x));
            dv.y = __uint_as_float(f2tf32(v.y));
            dv.z = __uint_as_float(f2tf32(v.z));
            dv.w = __uint_as_float(f2tf32(v.w));
        } else {
            dv.x = dv.y = dv.z = dv.w = 0.f;
        }
        ((float4*)(g_Bt + (size_t)row*DD))[k4] = dv;
    }
}

// ---------------- K0b: dense gather of emb rows (VALIDATED R14) ------------
__global__ void k_gather(const int* __restrict__ ids,
                         const float* __restrict__ emb) {
    int row = blockIdx.x;
    int id  = ids[row];
    ((float4*)(g_E + (size_t)row*(2*DD)))[threadIdx.x] =
        ((const float4*)(emb + (size_t)id*(2*DD)))[threadIdx.x];
}

// ---------------- K1: elementwise recurrence (VALIDATED R14) ---------------
__global__ void k_recur(float* __restrict__ out) {
    __shared__ float2 stab[RESN];
    const int b = blockIdx.x;     // 8 blocks
    const int d = threadIdx.x;    // 128 threads
    for (int i = threadIdx.x; i < RESN; i += 128) stab[i] = g_tab[i];
    __syncthreads();

    const float* eb = g_E + (size_t)(b*SS)*(2*DD);

    float hr = 0.f, hi = 0.f;
    float w0 = eb[d],            b0 = eb[DD + d];            // t = 0
    float w1 = eb[2*DD + d],     b1 = eb[2*DD + DD + d];     // t = 1

    for (int t = 0; t < SS; t++) {
        float wn = 0.f, bn = 0.f;
        if (t + 2 < SS) {
            const float* ep = eb + (size_t)(t + 2)*(2*DD);
            wn = ep[d];
            bn = ep[DD + d];
        }
        float div   = __fdiv_rn(__fadd_rn(hr, hi), __fadd_rn(1.0f, fabsf(w0)));
        float tphi  = __fmul_rn((float)t, PHI_F);
        float theta = __fadd_rn(__fadd_rn(div, b0), tphi);
        int ii = __float2int_rn(__fmul_rn(theta, CSC_F)) & (RESN - 1);
        float2 sc = stab[ii];
        hi = sc.x; hr = sc.y;
        g_X[(b*SS + t)*DD + d] = __fadd_rn(hr, hi);
        w0 = w1; b0 = b1; w1 = wn; b1 = bn;
    }
    out[HOFF + b*DD + d]           = hr;
    out[HOFF + BB*DD + b*DD + d]   = hi;
}

// ---------------- K2: fused 2-layer MLP, v3 --------------------------------
// Same per-element accumulation orders as R13/R15 (bit-identical results):
// phase1 k-ascending, phase2 j-ascending with (c*wr) before (s*wi) per j.
// NEW: weights streamed through smem via double-buffered cp.async chunks
// (phase1: 8 x 16KB of Wt; phase2: 16 x (8KB Wr + 8KB Wi)). All weight reads
// become conflict-free LDS; gmem latency leaves the critical path.
#define TM 8
#define MLP_SMEM (13312*4)     // xs 1024 + cs 2048 + sn 2048 + wbuf 8192 floats
__global__ __launch_bounds__(256) void k_mlp(const float* __restrict__ bvec) {
    extern __shared__ float sm[];
    float* xs   = sm;            // [8][128]
    float* cs   = sm + 1024;     // [8][256]
    float* sn   = sm + 3072;     // [8][256]
    float* wbuf = sm + 5120;     // [2][4096]
    const unsigned wb_s = (unsigned)__cvta_generic_to_shared(wbuf);
    const int tid = threadIdx.x;
    const int r0  = blockIdx.x * TM;

    for (int i = tid; i < TM*DD; i += 256)
        xs[i] = g_X[r0*DD + i];
    // visibility of xs provided by the first wait+sync inside the layer loop

    for (int l = 0; l < LL; l++) {
        // ======== phase 1: th[r][j] (thread = j), Wt streamed ========
        {
            const float* src = g_Wt + l*DD*NN;      // chunk 0: k in [0,16)
            #pragma unroll
            for (int u = 0; u < 4; u++)
                cpa16(wb_s + (unsigned)(tid + u*256)*16u, src + (tid + u*256)*4);
            asm volatile("cp.async.commit_group;" ::: "memory");
        }
        float acc[TM];
        #pragma unroll
        for (int r = 0; r < TM; r++) acc[r] = 0.f;

        for (int c = 0; c < 8; c++) {
            asm volatile("cp.async.wait_group 0;" ::: "memory");
            __syncthreads();
            if (c < 7) {
                const float* src = g_Wt + l*DD*NN + (c + 1)*4096;
                unsigned dst = wb_s + (unsigned)(((c + 1) & 1)*4096)*4u;
                #pragma unroll
                for (int u = 0; u < 4; u++)
                    cpa16(dst + (unsigned)(tid + u*256)*16u, src + (tid + u*256)*4);
                asm volatile("cp.async.commit_group;" ::: "memory");
            }
            const float* wb = wbuf + (c & 1)*4096;   // [16][256]
            #pragma unroll
            for (int q = 0; q < 4; q++) {
                int k4 = c*4 + q;
                float4 xv[TM];
                #pragma unroll
                for (int r = 0; r < TM; r++)
                    xv[r] = ((const float4*)(xs + r*DD))[k4];
                float wv0 = wb[(q*4 + 0)*NN + tid];
                float wv1 = wb[(q*4 + 1)*NN + tid];
                float wv2 = wb[(q*4 + 2)*NN + tid];
                float wv3 = wb[(q*4 + 3)*NN + tid];
                #pragma unroll
                for (int r = 0; r < TM; r++) {
                    acc[r] += xv[r].x * wv0;
                    acc[r] += xv[r].y * wv1;
                    acc[r] += xv[r].z * wv2;
                    acc[r] += xv[r].w * wv3;
                }
            }
        }
        float bj = bvec[l*NN + tid];
        #pragma unroll
        for (int r = 0; r < TM; r++) {
            float tphi = (float)((r0 + r) & (SS-1)) * PHI_F;
            float th = (acc[r] + bj) + tphi;
            int ii = __float2int_rn(th * CSC_F) & (RESN - 1);
            float2 sc = g_tab[ii];
            sn[r*NN + tid] = sc.x;
            cs[r*NN + tid] = sc.y;
        }
        // sn/cs visibility: covered by phase-2 chunk-0 wait+sync below.

        // ======== phase 2: o[r][d] (thread = (r, 4d)), Wr/Wi streamed ========
        {
            const float* srcR = g_Wrt + l*NN*DD;    // chunk 0: j in [0,16)
            const float* srcI = g_Wit + l*NN*DD;
            #pragma unroll
            for (int u = 0; u < 2; u++) {
                cpa16(wb_s + (unsigned)(tid + u*256)*16u, srcR + (tid + u*256)*4);
                cpa16(wb_s + 2048u*4u + (unsigned)(tid + u*256)*16u,
                      srcI + (tid + u*256)*4);
            }
            asm volatile("cp.async.commit_group;" ::: "memory");
        }
        const int dg = tid & 31;      // 4 consecutive d per thread
        const int r2 = tid >> 5;      // one row per warp
        float o0 = 0.f, o1 = 0.f, o2 = 0.f, o3 = 0.f;

        for (int c = 0; c < 16; c++) {
            asm volatile("cp.async.wait_group 0;" ::: "memory");
            __syncthreads();
            if (c < 15) {
                const float* srcR = g_Wrt + l*NN*DD + (c + 1)*2048;
                const float* srcI = g_Wit + l*NN*DD + (c + 1)*2048;
                unsigned dst = wb_s + (unsigned)(((c + 1) & 1)*4096)*4u;
                #pragma unroll
                for (int u = 0; u < 2; u++) {
                    cpa16(dst + (unsigned)(tid + u*256)*16u, srcR + (tid + u*256)*4);
                    cpa16(dst + 2048u*4u + (unsigned)(tid + u*256)*16u,
                          srcI + (tid + u*256)*4);
                }
                asm volatile("cp.async.commit_group;" ::: "memory");
            }
            const float* wrb = wbuf + (c & 1)*4096;  // [16][128]
            const float* wib = wrb + 2048;           // [16][128]
            #pragma unroll
            for (int q = 0; q < 4; q++) {
                int j4 = c*4 + q;
                float4 cv = ((const float4*)(cs + r2*NN))[j4];
                float4 sv = ((const float4*)(sn + r2*NN))[j4];
                #pragma unroll
                for (int jj = 0; jj < 4; jj++) {
                    float4 a  = ((const float4*)(wrb + (q*4 + jj)*DD))[dg];
                    float4 b2 = ((const float4*)(wib + (q*4 + jj)*DD))[dg];
                    float cc = (jj == 0) ? cv.x : (jj == 1) ? cv.y :
                               (jj == 2) ? cv.z : cv.w;
                    float ss = (jj == 0) ? sv.x : (jj == 1) ? sv.y :
                               (jj == 2) ? sv.z : sv.w;
                    o0 += cc*a.x + ss*b2.x;
                    o1 += cc*a.y + ss*b2.y;
                    o2 += cc*a.z + ss*b2.z;
                    o3 += cc*a.w + ss*b2.w;
                }
            }
        }
        {
            int dbase = dg * 4;
            float ov[4] = {o0, o1, o2, o3};
            #pragma unroll
            for (int q = 0; q < 4; q++) {
                float o = ov[q];
                float sg = 1.0f / (1.0f + expf(-o));
                xs[r2*DD + dbase + q] += o * sg;
            }
        }
        // xs visibility for next layer: covered by next phase-1 wait+sync.
    }
    __syncthreads();
    // write-back pre-rounded to tf32 (bit pattern is a valid f32)
    for (int i = tid; i < TM*DD; i += 256)
        g_X[r0*DD + i] = __uint_as_float(f2tf32(xs[i]));
}

// ---------------- K3: logits GEMM (VALIDATED R13, 219.5us). Frozen. --------
#define PA 132
#define K3_SMEM ((64*PA + 128*PA)*4)     // 101376 B -> 2 CTAs/SM
#define K3_GRID 296
#define K3_ITEMS (NTT*32)                // 12576 (393 nt x 32 m-chunks of 64)

__device__ __forceinline__ void ldsm_x4(unsigned& r0, unsigned& r1,
                                        unsigned& r2, unsigned& r3, unsigned addr) {
    asm volatile("ldmatrix.sync.aligned.m8n8.x4.shared.b16 {%0,%1,%2,%3}, [%4];"
                 : "=r"(r0), "=r"(r1), "=r"(r2), "=r"(r3) : "r"(addr));
}

__global__ __launch_bounds__(256, 2) void k_gemm(const float* __restrict__ Bmat,
                                                 float* __restrict__ out) {
    extern __shared__ unsigned smemu[];
    float* Os = (float*)smemu;               // 64 x 129 floats, aliases As region

    const int tid  = threadIdx.x;
    const int warp = tid >> 5, lane = tid & 31;
    const int grp  = lane >> 2, tig = lane & 3;
    const int wm   = (warp >> 2) * 32;       // warp row base (0 or 32)
    const int wn   = (warp & 3) * 32;        // warp col base (0,32,64,96)

    const unsigned sbase  = (unsigned)__cvta_generic_to_shared(smemu);
    const unsigned bs_u32 = sbase + 64u*PA*4u;

    const unsigned aBase = sbase + (unsigned)((wm + (lane & 15))*PA)*4u
                                 + (unsigned)(lane >> 4)*16u;
    const unsigned bBase = bs_u32 + (unsigned)((wn + ((lane >> 4) & 1)*8 + (lane & 7))*PA)*4u
                                  + (unsigned)((lane >> 3) & 1)*16u;

    const int start = (int)(((long long)blockIdx.x       * K3_ITEMS) / K3_GRID);
    const int stop  = (int)(((long long)(blockIdx.x + 1) * K3_ITEMS) / K3_GRID);
    if (start >= stop) return;

    {
        const float* src = g_X + (size_t)((start & 31) * 64) * DD;
        #pragma unroll
        for (int it = 0; it < 8; it++) {
            int c = tid + it*256;                // 2048 16B chunks (64 rows)
            int r = c >> 5, k4 = c & 31;
            cpa16(sbase + (unsigned)(r*PA + k4*4)*4u, src + r*DD + k4*4);
        }
        asm volatile("cp.async.commit_group;" ::: "memory");
    }

    int cur_nt = -1;
    for (int item = start; item < stop; item++) {
        const int nt = item >> 5, mc = item & 31;
        const int n0 = nt * 128, m0 = mc * 64;

        asm volatile("cp.async.wait_group 0;" ::: "memory");
        __syncthreads();      // A visible to all

        if (nt != cur_nt) {   // stage B: pure async copy from padded g_Bt
            #pragma unroll
            for (int it = 0; it < 16; it++) {
                int c = tid + it*256;            // 4096 chunks (128 rows)
                int r = c >> 5, k4 = c & 31;
                cpa16(bs_u32 + (unsigned)(r*PA + k4*4)*4u,
                      g_Bt + (size_t)(n0 + r)*DD + k4*4);
            }
            asm volatile("cp.async.commit_group;" ::: "memory");
            asm volatile("cp.async.wait_group 0;" ::: "memory");
            cur_nt = nt;
            __syncthreads();
        }

        float acc[2][4][4];
        #pragma unroll
        for (int mi = 0; mi < 2; mi++)
            #pragma unroll
            for (int ni = 0; ni < 4; ni++)
                #pragma unroll
                for (int q = 0; q < 4; q++) acc[mi][ni][q] = 0.f;

        #pragma unroll
        for (int kk = 0; kk < 16; kk++) {
            const unsigned koff = kk * 32u;
            unsigned a[2][4], b[2][4];
            ldsm_x4(a[0][0], a[0][1], a[0][2], a[0][3], aBase + koff);
            ldsm_x4(a[1][0], a[1][1], a[1][2], a[1][3], aBase + 16u*PA*4u + koff);
            ldsm_x4(b[0][0], b[0][1], b[0][2], b[0][3], bBase + koff);
            ldsm_x4(b[1][0], b[1][1], b[1][2], b[1][3], bBase + 16u*PA*4u + koff);
            #pragma unroll
            for (int ni = 0; ni < 4; ni++) {
                unsigned b0 = b[ni >> 1][(ni & 1)*2];
                unsigned b1 = b[ni >> 1][(ni & 1)*2 + 1];
                #pragma unroll
                for (int mi = 0; mi < 2; mi++) {
                    asm volatile(
                        "mma.sync.aligned.m16n8k8.row.col.f32.tf32.tf32.f32 "
                        "{%0,%1,%2,%3}, {%4,%5,%6,%7}, {%8,%9}, {%0,%1,%2,%3};"
                        : "+f"(acc[mi][ni][0]), "+f"(acc[mi][ni][1]),
                          "+f"(acc[mi][ni][2]), "+f"(acc[mi][ni][3])
                        : "r"(a[mi][0]), "r"(a[mi][1]), "r"(a[mi][2]), "r"(a[mi][3]),
                          "r"(b0), "r"(b1));
                }
            }
        }
        __syncthreads();      // all LDSM reads of As done (Os aliases As)

        #pragma unroll
        for (int mi = 0; mi < 2; mi++) {
            #pragma unroll
            for (int ni = 0; ni < 4; ni++) {
                int rr = wm + mi*16 + grp;
                int cc = wn + ni*8 + 2*tig;
                Os[rr*129 + cc]       = acc[mi][ni][0];
                Os[rr*129 + cc + 1]   = acc[mi][ni][1];
                Os[(rr+8)*129 + cc]   = acc[mi][ni][2];
                Os[(rr+8)*129 + cc+1] = acc[mi][ni][3];
            }
        }
        __syncthreads();

        #pragma unroll 4
        for (int i = tid; i < 64*128; i += 256) {
            int r = i >> 7, c = i & 127;
            int col = n0 + c;
            if (col < VV)
                out[(size_t)(m0 + r)*VV + col] = Os[r*129 + c];
        }
        __syncthreads();      // Os reads done before next A overwrites region

        if (item + 1 < stop) {
            const float* src = g_X + (size_t)(((item + 1) & 31) * 64) * DD;
            #pragma unroll
            for (int it = 0; it < 8; it++) {
                int c = tid + it*256;
                int r = c >> 5, k4 = c & 31;
                cpa16(sbase + (unsigned)(r*PA + k4*4)*4u, src + r*DD + k4*4);
            }
            asm volatile("cp.async.commit_group;" ::: "memory");
        }
    }
}

// ---------------- launch ---------------------------------------------------
extern "C" void kernel_launch(void* const* d_in, const int* in_sizes, int n_in,
                              void* d_out, int out_size) {
    const int*   ids = (const int*)  d_in[0];
    const float* emb = (const float*)d_in[1];
    const float* W   = (const float*)d_in[2];
    const float* bv  = (const float*)d_in[3];
    const float* Wr  = (const float*)d_in[4];
    const float* Wi  = (const float*)d_in[5];
    const float* ow  = (const float*)d_in[6];
    float* out = (float*)d_out;

    (void)cudaFuncSetAttribute(k_gemm, cudaFuncAttributeMaxDynamicSharedMemorySize, K3_SMEM);
    (void)cudaFuncSetAttribute(k_mlp,  cudaFuncAttributeMaxDynamicSharedMemorySize, MLP_SMEM);

    k_init  <<<784, 256>>>(W, Wr, Wi, ow);
    k_gather<<<MM, 64>>>(ids, emb);
    k_recur <<<BB, 128>>>(out);
    k_mlp   <<<MM/TM, 256, MLP_SMEM>>>(bv);
    k_gemm  <<<K3_GRID, 256, K3_SMEM>>>(ow, out);
}